// round 2
// baseline (speedup 1.0000x reference)
#include <cuda_runtime.h>
#include <math.h>

// Problem dims (fixed by the dataset)
#define BDIM 4096
#define CDIM 1000
#define DDIM 2048
#define NDIM (BDIM + CDIM)   // 5096 supports
#define SEL_CAP 5120         // >= NDIM, per-class member cap (total members == NDIM)

// ---------------- scratch (device globals; no allocs allowed) ----------------
__device__ float g_pw[CDIM * CDIM];      // W @ W^T logits
__device__ float g_pz[BDIM * CDIM];      // z @ W^T logits
__device__ float g_ent[NDIM];            // entropies (W rows then z rows)
__device__ int   g_yhat[NDIM];           // argmax class
__device__ float g_rnorm[NDIM];          // 1 / max(||support||, eps)
__device__ float g_wT[CDIM * DDIM];      // weights^T: [C][D], row c = column c of weights

// ---------------- GEMM: C[M,N] = A[M,K] * B[N,K]^T (both K-major) ----------------
#define GBM 128
#define GBN 128
#define GBK 16
// 256 threads, 8x8 microtile per thread

__global__ __launch_bounds__(256) void gemm_nt(const float* __restrict__ A,
                                               const float* __restrict__ B,
                                               float* __restrict__ C,
                                               int M, int N, int K) {
    __shared__ float As[GBK][GBM + 4];
    __shared__ float Bs[GBK][GBN + 4];
    int tid = threadIdx.x;
    int tx = tid & 15, ty = tid >> 4;
    int bm = blockIdx.y * GBM, bn = blockIdx.x * GBN;

    float acc[8][8];
#pragma unroll
    for (int i = 0; i < 8; i++)
#pragma unroll
        for (int j = 0; j < 8; j++) acc[i][j] = 0.f;

    int lr0 = tid >> 2;           // 0..63 (plus +64 second half)
    int lk  = (tid & 3) * 4;      // 0,4,8,12

    for (int k0 = 0; k0 < K; k0 += GBK) {
#pragma unroll
        for (int half = 0; half < 2; half++) {
            int r = lr0 + half * 64;
            float4 va = make_float4(0.f, 0.f, 0.f, 0.f);
            if (bm + r < M) va = *(const float4*)(A + (size_t)(bm + r) * K + k0 + lk);
            As[lk + 0][r] = va.x; As[lk + 1][r] = va.y;
            As[lk + 2][r] = va.z; As[lk + 3][r] = va.w;
            float4 vb = make_float4(0.f, 0.f, 0.f, 0.f);
            if (bn + r < N) vb = *(const float4*)(B + (size_t)(bn + r) * K + k0 + lk);
            Bs[lk + 0][r] = vb.x; Bs[lk + 1][r] = vb.y;
            Bs[lk + 2][r] = vb.z; Bs[lk + 3][r] = vb.w;
        }
        __syncthreads();

#pragma unroll
        for (int k = 0; k < GBK; k++) {
            float4 a0 = *(const float4*)(&As[k][ty * 8]);
            float4 a1 = *(const float4*)(&As[k][ty * 8 + 4]);
            float4 b0 = *(const float4*)(&Bs[k][tx * 8]);
            float4 b1 = *(const float4*)(&Bs[k][tx * 8 + 4]);
            float a[8] = {a0.x, a0.y, a0.z, a0.w, a1.x, a1.y, a1.z, a1.w};
            float b[8] = {b0.x, b0.y, b0.z, b0.w, b1.x, b1.y, b1.z, b1.w};
#pragma unroll
            for (int i = 0; i < 8; i++)
#pragma unroll
                for (int j = 0; j < 8; j++)
                    acc[i][j] = fmaf(a[i], b[j], acc[i][j]);
        }
        __syncthreads();
    }

#pragma unroll
    for (int i = 0; i < 8; i++) {
        int row = bm + ty * 8 + i;
        if (row < M) {
#pragma unroll
            for (int j = 0; j < 8; j++) {
                int col = bn + tx * 8 + j;
                if (col < N) C[(size_t)row * N + col] = acc[i][j];
            }
        }
    }
}

// ---------------- per-row entropy + argmax (stable, streaming) ----------------
// H = log(s) - t/s with m = max, s = sum exp(l-m), t = sum (l-m) exp(l-m)
__global__ __launch_bounds__(256) void row_stats(const float* __restrict__ L,
                                                 int ncols, int offset) {
    int row = blockIdx.x;
    const float* l = L + (size_t)row * ncols;
    __shared__ float sv[256];
    __shared__ int   si[256];
    __shared__ float sw[256];
    int tid = threadIdx.x;

    float best = -3.4e38f; int bidx = 0x7fffffff;
    for (int c = tid; c < ncols; c += 256) {
        float v = l[c];
        if (v > best || (v == best && c < bidx)) { best = v; bidx = c; }
    }
    sv[tid] = best; si[tid] = bidx;
    __syncthreads();
    for (int s = 128; s > 0; s >>= 1) {
        if (tid < s) {
            float v = sv[tid + s]; int ix = si[tid + s];
            if (v > sv[tid] || (v == sv[tid] && ix < si[tid])) { sv[tid] = v; si[tid] = ix; }
        }
        __syncthreads();
    }
    float m = sv[0]; int am = si[0];
    __syncthreads();

    float s1 = 0.f, s2 = 0.f;
    for (int c = tid; c < ncols; c += 256) {
        float d = l[c] - m;
        float e = expf(d);
        s1 += e; s2 += e * d;
    }
    sv[tid] = s1; sw[tid] = s2;
    __syncthreads();
    for (int s = 128; s > 0; s >>= 1) {
        if (tid < s) { sv[tid] += sv[tid + s]; sw[tid] += sw[tid + s]; }
        __syncthreads();
    }
    if (tid == 0) {
        float S = sv[0], T = sw[0];
        g_ent[offset + row]  = logf(S) - T / S;
        g_yhat[offset + row] = am;
    }
}

// ---------------- support inverse norms ----------------
__global__ __launch_bounds__(256) void support_rnorm(const float* __restrict__ W,
                                                     const float* __restrict__ z) {
    int j = blockIdx.x;
    const float* row = (j < CDIM) ? (W + (size_t)j * DDIM)
                                  : (z + (size_t)(j - CDIM) * DDIM);
    __shared__ float red[256];
    int tid = threadIdx.x;
    float ss = 0.f;
    for (int d = tid; d < DDIM; d += 256) { float v = row[d]; ss += v * v; }
    red[tid] = ss;
    __syncthreads();
    for (int s = 128; s > 0; s >>= 1) {
        if (tid < s) red[tid] += red[tid + s];
        __syncthreads();
    }
    if (tid == 0) g_rnorm[j] = 1.f / fmaxf(sqrtf(red[0]), 1e-12f);
}

// ---------------- per-class selection + prototype accumulation ----------------
// One block per class. Collect members (yhat==c), keep K lowest-entropy
// (tie-break: lower support index first, matching jax.lax.top_k), sum their
// L2-normalized vectors, L2-normalize the column, write weights^T row c.
__global__ __launch_bounds__(256) void select_accum(const float* __restrict__ W,
                                                    const float* __restrict__ z,
                                                    const int* __restrict__ filterK) {
    __shared__ float ent_s[SEL_CAP];
    __shared__ int   idx_s[SEL_CAP];
    __shared__ unsigned char keep_s[SEL_CAP];
    __shared__ int   cnt;
    __shared__ float red[256];

    int c = blockIdx.x;
    int tid = threadIdx.x;
    if (tid == 0) cnt = 0;
    __syncthreads();

    for (int j = tid; j < NDIM; j += 256) {
        if (g_yhat[j] == c) {
            int p = atomicAdd(&cnt, 1);
            if (p < SEL_CAP) { ent_s[p] = g_ent[j]; idx_s[p] = j; }
        }
    }
    __syncthreads();
    int n = min(cnt, SEL_CAP);
    int K = *filterK;

    // rank-based selection: keep if fewer than K strictly-better members
    for (int i = tid; i < n; i += 256) {
        float ei = ent_s[i]; int ji = idx_s[i];
        int rank = 0;
        for (int m2 = 0; m2 < n; m2++) {
            float em = ent_s[m2]; int jm = idx_s[m2];
            rank += (em < ei) || (em == ei && jm < ji);
        }
        keep_s[i] = (rank < K) ? 1 : 0;
    }
    __syncthreads();

    // accumulate normalized supports; each thread owns DDIM/256 = 8 dims
    float acc[DDIM / 256];
#pragma unroll
    for (int u = 0; u < DDIM / 256; u++) acc[u] = 0.f;

    for (int i = 0; i < n; i++) {
        if (!keep_s[i]) continue;
        int j = idx_s[i];
        const float* srow = (j < CDIM) ? (W + (size_t)j * DDIM)
                                       : (z + (size_t)(j - CDIM) * DDIM);
        float rn = g_rnorm[j];
#pragma unroll
        for (int u = 0; u < DDIM / 256; u++)
            acc[u] = fmaf(srow[tid + u * 256], rn, acc[u]);
    }

    // column L2 norm
    float ss = 0.f;
#pragma unroll
    for (int u = 0; u < DDIM / 256; u++) ss += acc[u] * acc[u];
    red[tid] = ss;
    __syncthreads();
    for (int s = 128; s > 0; s >>= 1) {
        if (tid < s) red[tid] += red[tid + s];
        __syncthreads();
    }
    float inv = 1.f / fmaxf(sqrtf(red[0]), 1e-12f);
#pragma unroll
    for (int u = 0; u < DDIM / 256; u++)
        g_wT[(size_t)c * DDIM + tid + u * 256] = acc[u] * inv;
}

// ---------------- launch ----------------
extern "C" void kernel_launch(void* const* d_in, const int* in_sizes, int n_in,
                              void* d_out, int out_size) {
    const float* z  = (const float*)d_in[0];   // [4096, 2048]
    const float* W  = (const float*)d_in[1];   // [1000, 2048]
    const int*   fK = (const int*)d_in[2];     // scalar filter_K
    float* out = (float*)d_out;                // [4096, 1000]

    float *pw, *pz, *wT;
    cudaGetSymbolAddress((void**)&pw, g_pw);
    cudaGetSymbolAddress((void**)&pz, g_pz);
    cudaGetSymbolAddress((void**)&wT, g_wT);

    dim3 thr(256);
    // warmup logits + stats
    {
        dim3 grid((CDIM + GBN - 1) / GBN, (CDIM + GBM - 1) / GBM);
        gemm_nt<<<grid, thr>>>(W, W, pw, CDIM, CDIM, DDIM);
    }
    row_stats<<<CDIM, thr>>>(pw, CDIM, 0);
    // test-batch logits + stats
    {
        dim3 grid((CDIM + GBN - 1) / GBN, (BDIM + GBM - 1) / GBM);
        gemm_nt<<<grid, thr>>>(z, W, pz, BDIM, CDIM, DDIM);
    }
    row_stats<<<BDIM, thr>>>(pz, CDIM, CDIM);
    // support norms
    support_rnorm<<<NDIM, thr>>>(W, z);
    // per-class selection + prototype build
    select_accum<<<CDIM, thr>>>(W, z, fK);
    // final logits: out = z @ weights  (== z [B,D] * wT [C,D]^T)
    {
        dim3 grid((CDIM + GBN - 1) / GBN, (BDIM + GBM - 1) / GBM);
        gemm_nt<<<grid, thr>>>(z, wT, out, BDIM, CDIM, DDIM);
    }
}

// round 5
// speedup vs baseline: 2.4139x; 2.4139x over previous
#include <cuda_runtime.h>
#include <cuda_bf16.h>
#include <math.h>
#include <stdint.h>

// Problem dims (fixed by the dataset)
#define BDIM 4096
#define CDIM 1000
#define DDIM 2048
#define NDIM (BDIM + CDIM)   // 5096 supports
#define SEL_CAP 5120

// ---------------- scratch (device globals; no allocs allowed) ----------------
__device__ float g_pw[CDIM * CDIM];
__device__ float g_pz[BDIM * CDIM];
__device__ float g_ent[NDIM];
__device__ int   g_yhat[NDIM];
__device__ float g_rnorm[NDIM];
__device__ __nv_bfloat16 g_zhi[BDIM * DDIM];
__device__ __nv_bfloat16 g_zlo[BDIM * DDIM];
__device__ __nv_bfloat16 g_Whi[CDIM * DDIM];
__device__ __nv_bfloat16 g_Wlo[CDIM * DDIM];
__device__ __nv_bfloat16 g_Phi[CDIM * DDIM];   // prototype (weights^T) hi
__device__ __nv_bfloat16 g_Plo[CDIM * DDIM];   // prototype lo

// ================= helpers =================
__device__ __forceinline__ uint32_t smem_u32(const void* p) {
    uint32_t a;
    asm("{ .reg .u64 t; cvta.to.shared.u64 t, %1; cvt.u32.u64 %0, t; }" : "=r"(a) : "l"(p));
    return a;
}

__device__ __forceinline__ void cp16(uint32_t dst, const void* src, bool v) {
    int n = v ? 16 : 0;
    asm volatile("cp.async.cg.shared.global [%0], [%1], 16, %2;"
                 :: "r"(dst), "l"(src), "r"(n) : "memory");
}

#define LDSM4(r, addr) \
    asm volatile("ldmatrix.sync.aligned.m8n8.x4.shared.b16 {%0,%1,%2,%3}, [%4];" \
        : "=r"((r)[0]), "=r"((r)[1]), "=r"((r)[2]), "=r"((r)[3]) : "r"(addr))

#define MMA_BF16(acc, a, b) \
    asm volatile("mma.sync.aligned.m16n8k16.row.col.f32.bf16.bf16.f32 " \
        "{%0,%1,%2,%3}, {%4,%5,%6,%7}, {%8,%9}, {%0,%1,%2,%3};" \
        : "+f"((acc)[0]), "+f"((acc)[1]), "+f"((acc)[2]), "+f"((acc)[3]) \
        : "r"((a)[0]), "r"((a)[1]), "r"((a)[2]), "r"((a)[3]), \
          "r"((b)[0]), "r"((b)[1]))

// swizzled byte offset inside a 128-row x 128B tile (SW128 pattern)
__device__ __forceinline__ uint32_t swz(int row, int colbytes) {
    return (uint32_t)(row * 128 + (colbytes ^ ((row & 7) << 4)));
}

// ================= fp32 -> bf16 hi/lo split =================
__global__ __launch_bounds__(256) void split_bf16(const float4* __restrict__ src,
                                                  __nv_bfloat162* __restrict__ hi,
                                                  __nv_bfloat162* __restrict__ lo,
                                                  int n4) {
    int i = blockIdx.x * 256 + threadIdx.x;
    if (i >= n4) return;
    float4 v = src[i];
    __nv_bfloat162 h0 = __float22bfloat162_rn(make_float2(v.x, v.y));
    __nv_bfloat162 h1 = __float22bfloat162_rn(make_float2(v.z, v.w));
    float2 r0 = make_float2(v.x - __bfloat162float(h0.x), v.y - __bfloat162float(h0.y));
    float2 r1 = make_float2(v.z - __bfloat162float(h1.x), v.w - __bfloat162float(h1.y));
    hi[i * 2 + 0] = h0; hi[i * 2 + 1] = h1;
    lo[i * 2 + 0] = __float22bfloat162_rn(r0);
    lo[i * 2 + 1] = __float22bfloat162_rn(r1);
}

// ================= bf16x2 split GEMM on mma.sync =================
// C[M,N] = A[M,2048] * B[N,2048]^T, A/B given as bf16 hi/lo pairs.
// CTA 128x128, 8 warps of 64x32, K-tile 64, 3-stage cp.async pipeline.

#define KT 64
#define NKT (DDIM / KT)           // 32
#define TILE_B 16384              // 128 rows * 128 bytes
#define STG_B (4 * TILE_B)        // Ahi, Alo, Bhi, Blo
#define NSTAGE 3
#define SMEM_SZ (NSTAGE * STG_B)  // 196608

__global__ __launch_bounds__(256, 1)
void gemm_bf16x2(const __nv_bfloat16* __restrict__ Ahi, const __nv_bfloat16* __restrict__ Alo,
                 const __nv_bfloat16* __restrict__ Bhi, const __nv_bfloat16* __restrict__ Blo,
                 float* __restrict__ C, int M, int N) {
    extern __shared__ char smem[];
    uint32_t sb = smem_u32(smem);
    int tid = threadIdx.x, lane = tid & 31, wid = tid >> 5;
    int bm = blockIdx.y * 128, bn = blockIdx.x * 128;
    int wm = (wid >> 2) * 64, wn = (wid & 3) * 32;

    float acc[4][4][4];
#pragma unroll
    for (int mf = 0; mf < 4; mf++)
#pragma unroll
        for (int nf = 0; nf < 4; nf++)
#pragma unroll
            for (int q = 0; q < 4; q++) acc[mf][nf][q] = 0.f;

    // cp.async slot mapping: 4 chunks of 16B per tile per thread
    int crow[4], ccol[4]; uint32_t cdst[4];
#pragma unroll
    for (int it = 0; it < 4; it++) {
        int c = tid + it * 256;
        crow[it] = c >> 3; ccol[it] = c & 7;
        cdst[it] = swz(crow[it], ccol[it] * 16);
    }

#define PREFETCH(kt, s) do { \
    uint32_t st = sb + (uint32_t)(s) * STG_B; \
    int k0 = (kt) * KT; \
    _Pragma("unroll") \
    for (int it = 0; it < 4; it++) { \
        int ra = bm + crow[it], rb = bn + crow[it]; \
        size_t ga = (size_t)ra * DDIM + k0 + ccol[it] * 8; \
        size_t gb = (size_t)rb * DDIM + k0 + ccol[it] * 8; \
        cp16(st + 0 * TILE_B + cdst[it], Ahi + ga, ra < M); \
        cp16(st + 1 * TILE_B + cdst[it], Alo + ga, ra < M); \
        cp16(st + 2 * TILE_B + cdst[it], Bhi + gb, rb < N); \
        cp16(st + 3 * TILE_B + cdst[it], Blo + gb, rb < N); \
    } \
    asm volatile("cp.async.commit_group;"); \
} while (0)

    PREFETCH(0, 0);
    PREFETCH(1, 1);

    int lr = lane & 15, kadd = (lane >> 4) * 8;

    for (int kt = 0; kt < NKT; kt++) {
        if (kt < NKT - 2) asm volatile("cp.async.wait_group 1;");
        else              asm volatile("cp.async.wait_group 0;");
        __syncthreads();

        if (kt + 2 < NKT) PREFETCH(kt + 2, (kt + 2) % NSTAGE);

        uint32_t st = sb + (uint32_t)(kt % NSTAGE) * STG_B;
        uint32_t sAh = st, sAl = st + TILE_B, sBh = st + 2 * TILE_B, sBl = st + 3 * TILE_B;

#pragma unroll
        for (int ks = 0; ks < 4; ks++) {
            int kc = (ks * 16 + kadd) * 2;   // col byte offset
            uint32_t ah[4][4], al[4][4];
#pragma unroll
            for (int mf = 0; mf < 4; mf++) {
                int row = wm + mf * 16 + lr;
                uint32_t off = swz(row, kc);
                LDSM4(ah[mf], sAh + off);
                LDSM4(al[mf], sAl + off);
            }
            uint32_t bh[4][2], bl[4][2];
#pragma unroll
            for (int nb = 0; nb < 2; nb++) {
                int row = wn + nb * 16 + lr;
                uint32_t off = swz(row, kc);
                uint32_t t[4];
                LDSM4(t, sBh + off);
                bh[nb * 2][0] = t[0]; bh[nb * 2 + 1][0] = t[1];
                bh[nb * 2][1] = t[2]; bh[nb * 2 + 1][1] = t[3];
                LDSM4(t, sBl + off);
                bl[nb * 2][0] = t[0]; bl[nb * 2 + 1][0] = t[1];
                bl[nb * 2][1] = t[2]; bl[nb * 2 + 1][1] = t[3];
            }
#pragma unroll
            for (int mf = 0; mf < 4; mf++)
#pragma unroll
                for (int nf = 0; nf < 4; nf++) {
                    MMA_BF16(acc[mf][nf], ah[mf], bh[nf]);
                    MMA_BF16(acc[mf][nf], ah[mf], bl[nf]);
                    MMA_BF16(acc[mf][nf], al[mf], bh[nf]);
                }
        }
    }

    // epilogue: fragment (row = lane>>2 [+8], cols 2*(lane&3)+{0,1})
    int cr = lane >> 2, cc = (lane & 3) * 2;
#pragma unroll
    for (int mf = 0; mf < 4; mf++) {
#pragma unroll
        for (int nf = 0; nf < 4; nf++) {
            int col = bn + wn + nf * 8 + cc;
            if (col >= N) continue;
            int r0 = bm + wm + mf * 16 + cr;
            if (r0 < M)
                *(float2*)(C + (size_t)r0 * N + col) = make_float2(acc[mf][nf][0], acc[mf][nf][1]);
            int r1 = r0 + 8;
            if (r1 < M)
                *(float2*)(C + (size_t)r1 * N + col) = make_float2(acc[mf][nf][2], acc[mf][nf][3]);
        }
    }
#undef PREFETCH
}

// ---------------- per-row entropy + argmax (stable, streaming) ----------------
__global__ __launch_bounds__(256) void row_stats(const float* __restrict__ L,
                                                 int ncols, int offset) {
    int row = blockIdx.x;
    const float* l = L + (size_t)row * ncols;
    __shared__ float sv[256];
    __shared__ int   si[256];
    __shared__ float sw[256];
    int tid = threadIdx.x;

    float best = -3.4e38f; int bidx = 0x7fffffff;
    for (int c = tid; c < ncols; c += 256) {
        float v = l[c];
        if (v > best || (v == best && c < bidx)) { best = v; bidx = c; }
    }
    sv[tid] = best; si[tid] = bidx;
    __syncthreads();
    for (int s = 128; s > 0; s >>= 1) {
        if (tid < s) {
            float v = sv[tid + s]; int ix = si[tid + s];
            if (v > sv[tid] || (v == sv[tid] && ix < si[tid])) { sv[tid] = v; si[tid] = ix; }
        }
        __syncthreads();
    }
    float m = sv[0]; int am = si[0];
    __syncthreads();

    float s1 = 0.f, s2 = 0.f;
    for (int c = tid; c < ncols; c += 256) {
        float d = l[c] - m;
        float e = expf(d);
        s1 += e; s2 += e * d;
    }
    sv[tid] = s1; sw[tid] = s2;
    __syncthreads();
    for (int s = 128; s > 0; s >>= 1) {
        if (tid < s) { sv[tid] += sv[tid + s]; sw[tid] += sw[tid + s]; }
        __syncthreads();
    }
    if (tid == 0) {
        float S = sv[0], T = sw[0];
        g_ent[offset + row]  = logf(S) - T / S;
        g_yhat[offset + row] = am;
    }
}

// ---------------- support inverse norms ----------------
__global__ __launch_bounds__(256) void support_rnorm(const float* __restrict__ W,
                                                     const float* __restrict__ z) {
    int j = blockIdx.x;
    const float* row = (j < CDIM) ? (W + (size_t)j * DDIM)
                                  : (z + (size_t)(j - CDIM) * DDIM);
    __shared__ float red[256];
    int tid = threadIdx.x;
    float ss = 0.f;
    for (int d = tid; d < DDIM; d += 256) { float v = row[d]; ss += v * v; }
    red[tid] = ss;
    __syncthreads();
    for (int s = 128; s > 0; s >>= 1) {
        if (tid < s) red[tid] += red[tid + s];
        __syncthreads();
    }
    if (tid == 0) g_rnorm[j] = 1.f / fmaxf(sqrtf(red[0]), 1e-12f);
}

// ---------------- per-class selection + prototype accumulation ----------------
__global__ __launch_bounds__(256) void select_accum(const float* __restrict__ W,
                                                    const float* __restrict__ z,
                                                    const int* __restrict__ filterK) {
    __shared__ float ent_s[SEL_CAP];
    __shared__ int   idx_s[SEL_CAP];
    __shared__ unsigned char keep_s[SEL_CAP];
    __shared__ int   cnt;
    __shared__ float red[256];

    int c = blockIdx.x;
    int tid = threadIdx.x;
    if (tid == 0) cnt = 0;
    __syncthreads();

    for (int j = tid; j < NDIM; j += 256) {
        if (g_yhat[j] == c) {
            int p = atomicAdd(&cnt, 1);
            if (p < SEL_CAP) { ent_s[p] = g_ent[j]; idx_s[p] = j; }
        }
    }
    __syncthreads();
    int n = min(cnt, SEL_CAP);
    int K = *filterK;

    // rank-based selection: keep if fewer than K strictly-better members
    // (tie-break: lower support index first, matching jax.lax.top_k)
    for (int i = tid; i < n; i += 256) {
        float ei = ent_s[i]; int ji = idx_s[i];
        int rank = 0;
        for (int m2 = 0; m2 < n; m2++) {
            float em = ent_s[m2]; int jm = idx_s[m2];
            rank += (em < ei) || (em == ei && jm < ji);
        }
        keep_s[i] = (rank < K) ? 1 : 0;
    }
    __syncthreads();

    float acc[DDIM / 256];
#pragma unroll
    for (int u = 0; u < DDIM / 256; u++) acc[u] = 0.f;

    for (int i = 0; i < n; i++) {
        if (!keep_s[i]) continue;
        int j = idx_s[i];
        const float* srow = (j < CDIM) ? (W + (size_t)j * DDIM)
                                       : (z + (size_t)(j - CDIM) * DDIM);
        float rn = g_rnorm[j];
#pragma unroll
        for (int u = 0; u < DDIM / 256; u++)
            acc[u] = fmaf(srow[tid + u * 256], rn, acc[u]);
    }

    float ss = 0.f;
#pragma unroll
    for (int u = 0; u < DDIM / 256; u++) ss += acc[u] * acc[u];
    red[tid] = ss;
    __syncthreads();
    for (int s = 128; s > 0; s >>= 1) {
        if (tid < s) red[tid] += red[tid + s];
        __syncthreads();
    }
    float inv = 1.f / fmaxf(sqrtf(red[0]), 1e-12f);
#pragma unroll
    for (int u = 0; u < DDIM / 256; u++) {
        float v = acc[u] * inv;
        __nv_bfloat16 h = __float2bfloat16(v);
        g_Phi[(size_t)c * DDIM + tid + u * 256] = h;
        g_Plo[(size_t)c * DDIM + tid + u * 256] = __float2bfloat16(v - __bfloat162float(h));
    }
}

// ---------------- launch ----------------
extern "C" void kernel_launch(void* const* d_in, const int* in_sizes, int n_in,
                              void* d_out, int out_size) {
    const float* z  = (const float*)d_in[0];   // [4096, 2048]
    const float* W  = (const float*)d_in[1];   // [1000, 2048]
    const int*   fK = (const int*)d_in[2];     // scalar filter_K
    float* out = (float*)d_out;                // [4096, 1000]

    float *pw, *pz;
    __nv_bfloat16 *zhi, *zlo, *Whi, *Wlo, *Phi, *Plo;
    cudaGetSymbolAddress((void**)&pw,  g_pw);
    cudaGetSymbolAddress((void**)&pz,  g_pz);
    cudaGetSymbolAddress((void**)&zhi, g_zhi);
    cudaGetSymbolAddress((void**)&zlo, g_zlo);
    cudaGetSymbolAddress((void**)&Whi, g_Whi);
    cudaGetSymbolAddress((void**)&Wlo, g_Wlo);
    cudaGetSymbolAddress((void**)&Phi, g_Phi);
    cudaGetSymbolAddress((void**)&Plo, g_Plo);

    cudaFuncSetAttribute(gemm_bf16x2, cudaFuncAttributeMaxDynamicSharedMemorySize, SMEM_SZ);

    dim3 thr(256);
    // split inputs into bf16 hi/lo
    int n4z = BDIM * DDIM / 4, n4w = CDIM * DDIM / 4;
    split_bf16<<<(n4z + 255) / 256, thr>>>((const float4*)z,
        (__nv_bfloat162*)zhi, (__nv_bfloat162*)zlo, n4z);
    split_bf16<<<(n4w + 255) / 256, thr>>>((const float4*)W,
        (__nv_bfloat162*)Whi, (__nv_bfloat162*)Wlo, n4w);

    // warmup logits: W @ W^T  [1000 x 1000]
    gemm_bf16x2<<<dim3(8, 8), thr, SMEM_SZ>>>(Whi, Wlo, Whi, Wlo, pw, CDIM, CDIM);
    row_stats<<<CDIM, thr>>>(pw, CDIM, 0);
    // test logits: z @ W^T  [4096 x 1000]
    gemm_bf16x2<<<dim3(8, 32), thr, SMEM_SZ>>>(zhi, zlo, Whi, Wlo, pz, BDIM, CDIM);
    row_stats<<<BDIM, thr>>>(pz, CDIM, CDIM);
    // support norms + selection + prototypes (bf16 split emitted directly)
    support_rnorm<<<NDIM, thr>>>(W, z);
    select_accum<<<CDIM, thr>>>(W, z, fK);
    // final logits: z @ weights  [4096 x 1000]
    gemm_bf16x2<<<dim3(8, 32), thr, SMEM_SZ>>>(zhi, zlo, Phi, Plo, out, BDIM, CDIM);
}

// round 9
// speedup vs baseline: 2.5644x; 1.0623x over previous
#include <cuda_runtime.h>
#include <cuda_bf16.h>
#include <math.h>
#include <stdint.h>

// Problem dims (fixed by the dataset)
#define BDIM 4096
#define CDIM 1000
#define DDIM 2048
#define NDIM (BDIM + CDIM)   // 5096 supports
#define SEL_CAP 5120

// ---------------- scratch (device globals; no allocs allowed) ----------------
__device__ float g_pw[CDIM * CDIM];      // W@W^T partial (K-half 0)
__device__ float g_pw2[CDIM * CDIM];     // W@W^T partial (K-half 1)
__device__ float g_pz[BDIM * CDIM];
__device__ float g_ent[NDIM];
__device__ int   g_yhat[NDIM];
__device__ float g_rnorm[NDIM];
__device__ __nv_bfloat16 g_zhi[BDIM * DDIM];
__device__ __nv_bfloat16 g_zlo[BDIM * DDIM];
__device__ __nv_bfloat16 g_Whi[CDIM * DDIM];
__device__ __nv_bfloat16 g_Wlo[CDIM * DDIM];
__device__ __nv_bfloat16 g_Phi[CDIM * DDIM];
__device__ __nv_bfloat16 g_Plo[CDIM * DDIM];

// ================= helpers =================
__device__ __forceinline__ uint32_t smem_u32(const void* p) {
    uint32_t a;
    asm("{ .reg .u64 t; cvta.to.shared.u64 t, %1; cvt.u32.u64 %0, t; }" : "=r"(a) : "l"(p));
    return a;
}

__device__ __forceinline__ void cp16(uint32_t dst, const void* src, bool v) {
    int n = v ? 16 : 0;
    asm volatile("cp.async.cg.shared.global [%0], [%1], 16, %2;"
                 :: "r"(dst), "l"(src), "r"(n) : "memory");
}

#define LDSM4(r, addr) \
    asm volatile("ldmatrix.sync.aligned.m8n8.x4.shared.b16 {%0,%1,%2,%3}, [%4];" \
        : "=r"((r)[0]), "=r"((r)[1]), "=r"((r)[2]), "=r"((r)[3]) : "r"(addr))

#define MMA_BF16(acc, a, b) \
    asm volatile("mma.sync.aligned.m16n8k16.row.col.f32.bf16.bf16.f32 " \
        "{%0,%1,%2,%3}, {%4,%5,%6,%7}, {%8,%9}, {%0,%1,%2,%3};" \
        : "+f"((acc)[0]), "+f"((acc)[1]), "+f"((acc)[2]), "+f"((acc)[3]) \
        : "r"((a)[0]), "r"((a)[1]), "r"((a)[2]), "r"((a)[3]), \
          "r"((b)[0]), "r"((b)[1]))

// swizzled byte offset inside a 128-row x 128B tile (SW128 pattern)
__device__ __forceinline__ uint32_t swz(int row, int colbytes) {
    return (uint32_t)(row * 128 + (colbytes ^ ((row & 7) << 4)));
}

// ================= fp32 -> bf16 hi/lo split =================
__global__ __launch_bounds__(256) void split_bf16(const float4* __restrict__ src,
                                                  __nv_bfloat162* __restrict__ hi,
                                                  __nv_bfloat162* __restrict__ lo,
                                                  int n4) {
    int i = blockIdx.x * 256 + threadIdx.x;
    if (i >= n4) return;
    float4 v = src[i];
    __nv_bfloat162 h0 = __float22bfloat162_rn(make_float2(v.x, v.y));
    __nv_bfloat162 h1 = __float22bfloat162_rn(make_float2(v.z, v.w));
    float2 r0 = make_float2(v.x - __bfloat162float(h0.x), v.y - __bfloat162float(h0.y));
    float2 r1 = make_float2(v.z - __bfloat162float(h1.x), v.w - __bfloat162float(h1.y));
    hi[i * 2 + 0] = h0; hi[i * 2 + 1] = h1;
    lo[i * 2 + 0] = __float22bfloat162_rn(r0);
    lo[i * 2 + 1] = __float22bfloat162_rn(r1);
}

// ================= bf16x2 split GEMM on mma.sync =================
// C[M,N] = A[M,Kslice] * B[N,Kslice]^T over K slice [koff, koff+nkt*KT).
// blockIdx.z selects output buffer (C0/C1) and K-half for split-K.
// CTA 128x128, 8 warps of 64x32, K-tile 64, 3-stage cp.async pipeline.
// Passes are OUTER-looped so each accumulator reuse is 16 mma apart (RAW hidden).

#define KT 64
#define TILE_B 16384              // 128 rows * 128 bytes
#define STG_B (4 * TILE_B)        // Ahi, Alo, Bhi, Blo
#define NSTAGE 3
#define SMEM_SZ (NSTAGE * STG_B)  // 196608

__global__ __launch_bounds__(256, 1)
void gemm_bf16x2(const __nv_bfloat16* __restrict__ Ahi, const __nv_bfloat16* __restrict__ Alo,
                 const __nv_bfloat16* __restrict__ Bhi, const __nv_bfloat16* __restrict__ Blo,
                 float* __restrict__ C0, float* __restrict__ C1,
                 int M, int N, int nkt) {
    extern __shared__ char smem[];
    uint32_t sb = smem_u32(smem);
    int tid = threadIdx.x, lane = tid & 31, wid = tid >> 5;
    int bm = blockIdx.y * 128, bn = blockIdx.x * 128;
    int wm = (wid >> 2) * 64, wn = (wid & 3) * 32;
    int koff = blockIdx.z * nkt * KT;
    float* __restrict__ C = blockIdx.z ? C1 : C0;

    float acc[4][4][4];
#pragma unroll
    for (int mf = 0; mf < 4; mf++)
#pragma unroll
        for (int nf = 0; nf < 4; nf++)
#pragma unroll
            for (int q = 0; q < 4; q++) acc[mf][nf][q] = 0.f;

    // cp.async slot mapping: 4 chunks of 16B per tile per thread
    int crow[4], ccol[4]; uint32_t cdst[4];
#pragma unroll
    for (int it = 0; it < 4; it++) {
        int c = tid + it * 256;
        crow[it] = c >> 3; ccol[it] = c & 7;
        cdst[it] = swz(crow[it], ccol[it] * 16);
    }

#define PREFETCH(kt, s) do { \
    uint32_t st = sb + (uint32_t)(s) * STG_B; \
    int k0 = koff + (kt) * KT; \
    _Pragma("unroll") \
    for (int it = 0; it < 4; it++) { \
        int ra = bm + crow[it], rb = bn + crow[it]; \
        size_t ga = (size_t)ra * DDIM + k0 + ccol[it] * 8; \
        size_t gb = (size_t)rb * DDIM + k0 + ccol[it] * 8; \
        cp16(st + 0 * TILE_B + cdst[it], Ahi + ga, ra < M); \
        cp16(st + 1 * TILE_B + cdst[it], Alo + ga, ra < M); \
        cp16(st + 2 * TILE_B + cdst[it], Bhi + gb, rb < N); \
        cp16(st + 3 * TILE_B + cdst[it], Blo + gb, rb < N); \
    } \
    asm volatile("cp.async.commit_group;"); \
} while (0)

    PREFETCH(0, 0);
    PREFETCH(1, 1);

    int lr = lane & 15, kadd = (lane >> 4) * 8;

    for (int kt = 0; kt < nkt; kt++) {
        if (kt < nkt - 2) asm volatile("cp.async.wait_group 1;");
        else              asm volatile("cp.async.wait_group 0;");
        __syncthreads();

        if (kt + 2 < nkt) PREFETCH(kt + 2, (kt + 2) % NSTAGE);

        uint32_t st = sb + (uint32_t)(kt % NSTAGE) * STG_B;
        uint32_t sAh = st, sAl = st + TILE_B, sBh = st + 2 * TILE_B, sBl = st + 3 * TILE_B;

#pragma unroll
        for (int ks = 0; ks < 4; ks++) {
            int kc = (ks * 16 + kadd) * 2;   // col byte offset
            uint32_t ah[4][4], al[4][4];
#pragma unroll
            for (int mf = 0; mf < 4; mf++) {
                int row = wm + mf * 16 + lr;
                uint32_t off = swz(row, kc);
                LDSM4(ah[mf], sAh + off);
                LDSM4(al[mf], sAl + off);
            }
            uint32_t bh[4][2], bl[4][2];
#pragma unroll
            for (int nb = 0; nb < 2; nb++) {
                int row = wn + nb * 16 + lr;
                uint32_t off = swz(row, kc);
                uint32_t t[4];
                LDSM4(t, sBh + off);
                bh[nb * 2][0] = t[0]; bh[nb * 2 + 1][0] = t[1];
                bh[nb * 2][1] = t[2]; bh[nb * 2 + 1][1] = t[3];
                LDSM4(t, sBl + off);
                bl[nb * 2][0] = t[0]; bl[nb * 2 + 1][0] = t[1];
                bl[nb * 2][1] = t[2]; bl[nb * 2 + 1][1] = t[3];
            }
            // pass-major: accumulator reuse distance = 16 mma (RAW latency hidden)
#pragma unroll
            for (int mf = 0; mf < 4; mf++)
#pragma unroll
                for (int nf = 0; nf < 4; nf++)
                    MMA_BF16(acc[mf][nf], ah[mf], bh[nf]);
#pragma unroll
            for (int mf = 0; mf < 4; mf++)
#pragma unroll
                for (int nf = 0; nf < 4; nf++)
                    MMA_BF16(acc[mf][nf], ah[mf], bl[nf]);
#pragma unroll
            for (int mf = 0; mf < 4; mf++)
#pragma unroll
                for (int nf = 0; nf < 4; nf++)
                    MMA_BF16(acc[mf][nf], al[mf], bh[nf]);
        }
    }

    // epilogue
    int cr = lane >> 2, cc = (lane & 3) * 2;
#pragma unroll
    for (int mf = 0; mf < 4; mf++) {
#pragma unroll
        for (int nf = 0; nf < 4; nf++) {
            int col = bn + wn + nf * 8 + cc;
            if (col >= N) continue;
            int r0 = bm + wm + mf * 16 + cr;
            if (r0 < M)
                *(float2*)(C + (size_t)r0 * N + col) = make_float2(acc[mf][nf][0], acc[mf][nf][1]);
            int r1 = r0 + 8;
            if (r1 < M)
                *(float2*)(C + (size_t)r1 * N + col) = make_float2(acc[mf][nf][2], acc[mf][nf][3]);
        }
    }
#undef PREFETCH
}

// ---------------- per-row entropy + argmax (stable, streaming) ----------------
// Optional second logit buffer (split-K partial) summed on the fly.
__global__ __launch_bounds__(256) void row_stats(const float* __restrict__ L,
                                                 const float* __restrict__ L2,
                                                 int ncols, int offset) {
    int row = blockIdx.x;
    const float* l = L + (size_t)row * ncols;
    const float* l2 = L2 ? (L2 + (size_t)row * ncols) : nullptr;
    __shared__ float sv[256];
    __shared__ int   si[256];
    __shared__ float sw[256];
    int tid = threadIdx.x;

    float best = -3.4e38f; int bidx = 0x7fffffff;
    for (int c = tid; c < ncols; c += 256) {
        float v = l[c];
        if (l2) v += l2[c];
        if (v > best || (v == best && c < bidx)) { best = v; bidx = c; }
    }
    sv[tid] = best; si[tid] = bidx;
    __syncthreads();
    for (int s = 128; s > 0; s >>= 1) {
        if (tid < s) {
            float v = sv[tid + s]; int ix = si[tid + s];
            if (v > sv[tid] || (v == sv[tid] && ix < si[tid])) { sv[tid] = v; si[tid] = ix; }
        }
        __syncthreads();
    }
    float m = sv[0]; int am = si[0];
    __syncthreads();

    float s1 = 0.f, s2 = 0.f;
    for (int c = tid; c < ncols; c += 256) {
        float v = l[c];
        if (l2) v += l2[c];
        float d = v - m;
        float e = expf(d);
        s1 += e; s2 += e * d;
    }
    sv[tid] = s1; sw[tid] = s2;
    __syncthreads();
    for (int s = 128; s > 0; s >>= 1) {
        if (tid < s) { sv[tid] += sv[tid + s]; sw[tid] += sw[tid + s]; }
        __syncthreads();
    }
    if (tid == 0) {
        float S = sv[0], T = sw[0];
        g_ent[offset + row]  = logf(S) - T / S;
        g_yhat[offset + row] = am;
    }
}

// ---------------- support inverse norms ----------------
__global__ __launch_bounds__(256) void support_rnorm(const float* __restrict__ W,
                                                     const float* __restrict__ z) {
    int j = blockIdx.x;
    const float* row = (j < CDIM) ? (W + (size_t)j * DDIM)
                                  : (z + (size_t)(j - CDIM) * DDIM);
    __shared__ float red[256];
    int tid = threadIdx.x;
    float ss = 0.f;
    for (int d = tid; d < DDIM; d += 256) { float v = row[d]; ss += v * v; }
    red[tid] = ss;
    __syncthreads();
    for (int s = 128; s > 0; s >>= 1) {
        if (tid < s) red[tid] += red[tid + s];
        __syncthreads();
    }
    if (tid == 0) g_rnorm[j] = 1.f / fmaxf(sqrtf(red[0]), 1e-12f);
}

// ---------------- per-class selection + prototype accumulation ----------------
__global__ __launch_bounds__(256) void select_accum(const float* __restrict__ W,
                                                    const float* __restrict__ z,
                                                    const int* __restrict__ filterK) {
    __shared__ float ent_s[SEL_CAP];
    __shared__ int   idx_s[SEL_CAP];
    __shared__ unsigned char keep_s[SEL_CAP];
    __shared__ int   cnt;
    __shared__ float red[256];

    int c = blockIdx.x;
    int tid = threadIdx.x;
    if (tid == 0) cnt = 0;
    __syncthreads();

    for (int j = tid; j < NDIM; j += 256) {
        if (g_yhat[j] == c) {
            int p = atomicAdd(&cnt, 1);
            if (p < SEL_CAP) { ent_s[p] = g_ent[j]; idx_s[p] = j; }
        }
    }
    __syncthreads();
    int n = min(cnt, SEL_CAP);
    int K = *filterK;

    // rank-based selection (tie-break: lower support index, matching jax.lax.top_k)
    for (int i = tid; i < n; i += 256) {
        float ei = ent_s[i]; int ji = idx_s[i];
        int rank = 0;
        for (int m2 = 0; m2 < n; m2++) {
            float em = ent_s[m2]; int jm = idx_s[m2];
            rank += (em < ei) || (em == ei && jm < ji);
        }
        keep_s[i] = (rank < K) ? 1 : 0;
    }
    __syncthreads();

    float acc[DDIM / 256];
#pragma unroll
    for (int u = 0; u < DDIM / 256; u++) acc[u] = 0.f;

    for (int i = 0; i < n; i++) {
        if (!keep_s[i]) continue;
        int j = idx_s[i];
        const float* srow = (j < CDIM) ? (W + (size_t)j * DDIM)
                                       : (z + (size_t)(j - CDIM) * DDIM);
        float rn = g_rnorm[j];
#pragma unroll
        for (int u = 0; u < DDIM / 256; u++)
            acc[u] = fmaf(srow[tid + u * 256], rn, acc[u]);
    }

    float ss = 0.f;
#pragma unroll
    for (int u = 0; u < DDIM / 256; u++) ss += acc[u] * acc[u];
    red[tid] = ss;
    __syncthreads();
    for (int s = 128; s > 0; s >>= 1) {
        if (tid < s) red[tid] += red[tid + s];
        __syncthreads();
    }
    float inv = 1.f / fmaxf(sqrtf(red[0]), 1e-12f);
#pragma unroll
    for (int u = 0; u < DDIM / 256; u++) {
        float v = acc[u] * inv;
        __nv_bfloat16 h = __float2bfloat16(v);
        g_Phi[(size_t)c * DDIM + tid + u * 256] = h;
        g_Plo[(size_t)c * DDIM + tid + u * 256] = __float2bfloat16(v - __bfloat162float(h));
    }
}

// ---------------- launch ----------------
extern "C" void kernel_launch(void* const* d_in, const int* in_sizes, int n_in,
                              void* d_out, int out_size) {
    const float* z  = (const float*)d_in[0];   // [4096, 2048]
    const float* W  = (const float*)d_in[1];   // [1000, 2048]
    const int*   fK = (const int*)d_in[2];     // scalar filter_K
    float* out = (float*)d_out;                // [4096, 1000]

    float *pw, *pw2, *pz;
    __nv_bfloat16 *zhi, *zlo, *Whi, *Wlo, *Phi, *Plo;
    cudaGetSymbolAddress((void**)&pw,  g_pw);
    cudaGetSymbolAddress((void**)&pw2, g_pw2);
    cudaGetSymbolAddress((void**)&pz,  g_pz);
    cudaGetSymbolAddress((void**)&zhi, g_zhi);
    cudaGetSymbolAddress((void**)&zlo, g_zlo);
    cudaGetSymbolAddress((void**)&Whi, g_Whi);
    cudaGetSymbolAddress((void**)&Wlo, g_Wlo);
    cudaGetSymbolAddress((void**)&Phi, g_Phi);
    cudaGetSymbolAddress((void**)&Plo, g_Plo);

    cudaFuncSetAttribute(gemm_bf16x2, cudaFuncAttributeMaxDynamicSharedMemorySize, SMEM_SZ);

    dim3 thr(256);
    // split inputs into bf16 hi/lo
    int n4z = BDIM * DDIM / 4, n4w = CDIM * DDIM / 4;
    split_bf16<<<(n4z + 255) / 256, thr>>>((const float4*)z,
        (__nv_bfloat162*)zhi, (__nv_bfloat162*)zlo, n4z);
    split_bf16<<<(n4w + 255) / 256, thr>>>((const float4*)W,
        (__nv_bfloat162*)Whi, (__nv_bfloat162*)Wlo, n4w);

    // warmup logits: W @ W^T  [1000 x 1000], split-K x2 (128 CTAs, one wave)
    gemm_bf16x2<<<dim3(8, 8, 2), thr, SMEM_SZ>>>(Whi, Wlo, Whi, Wlo, pw, pw2, CDIM, CDIM, 16);
    row_stats<<<CDIM, thr>>>(pw, pw2, CDIM, 0);
    // test logits: z @ W^T  [4096 x 1000]
    gemm_bf16x2<<<dim3(8, 32, 1), thr, SMEM_SZ>>>(zhi, zlo, Whi, Wlo, pz, nullptr, BDIM, CDIM, 32);
    row_stats<<<BDIM, thr>>>(pz, nullptr, CDIM, CDIM);
    // support norms + selection + prototypes (bf16 split emitted directly)
    support_rnorm<<<NDIM, thr>>>(W, z);
    select_accum<<<CDIM, thr>>>(W, z, fK);
    // final logits: z @ weights  [4096 x 1000]
    gemm_bf16x2<<<dim3(8, 32, 1), thr, SMEM_SZ>>>(zhi, zlo, Phi, Plo, out, nullptr, BDIM, CDIM, 32);
}

// round 10
// speedup vs baseline: 6.2504x; 2.4374x over previous
#include <cuda_runtime.h>
#include <cuda_fp16.h>
#include <math.h>
#include <stdint.h>

// Problem dims (fixed by the dataset)
#define BDIM 4096
#define CDIM 1000
#define DDIM 2048
#define NDIM (BDIM + CDIM)   // 5096 supports
#define SEL_CAP 5120
#define NT1 36               // triangle tiles for W@W^T (8x8, r<=c)
#define NT2 256              // tiles for z@W^T (32x8)
#define GAP_TH 0.02f         // refine argmax when top-2 gap below this

// ---------------- scratch (device globals; no allocs allowed) ----------------
__device__ float  g_L[NDIM * CDIM];     // all logits: rows 0..999 = W@W^T, 1000.. = z@W^T
__device__ float  g_ent[NDIM];
__device__ int    g_yhat[NDIM];
__device__ float  g_rnorm[NDIM];
__device__ __half g_zh[BDIM * DDIM];
__device__ __half g_Wh[CDIM * DDIM];
__device__ __half g_Ph[CDIM * DDIM];    // prototype (weights^T) fp16

// ================= helpers =================
__device__ __forceinline__ uint32_t smem_u32(const void* p) {
    uint32_t a;
    asm("{ .reg .u64 t; cvta.to.shared.u64 t, %1; cvt.u32.u64 %0, t; }" : "=r"(a) : "l"(p));
    return a;
}

__device__ __forceinline__ void cp16(uint32_t dst, const void* src, bool v) {
    int n = v ? 16 : 0;
    asm volatile("cp.async.cg.shared.global [%0], [%1], 16, %2;"
                 :: "r"(dst), "l"(src), "r"(n) : "memory");
}

#define LDSM4(r, addr) \
    asm volatile("ldmatrix.sync.aligned.m8n8.x4.shared.b16 {%0,%1,%2,%3}, [%4];" \
        : "=r"((r)[0]), "=r"((r)[1]), "=r"((r)[2]), "=r"((r)[3]) : "r"(addr))

#define MMA_F16(acc, a, b) \
    asm volatile("mma.sync.aligned.m16n8k16.row.col.f32.f16.f16.f32 " \
        "{%0,%1,%2,%3}, {%4,%5,%6,%7}, {%8,%9}, {%0,%1,%2,%3};" \
        : "+f"((acc)[0]), "+f"((acc)[1]), "+f"((acc)[2]), "+f"((acc)[3]) \
        : "r"((a)[0]), "r"((a)[1]), "r"((a)[2]), "r"((a)[3]), \
          "r"((b)[0]), "r"((b)[1]))

// swizzled byte offset inside a 128-row x 128B tile (SW128 pattern)
__device__ __forceinline__ uint32_t swz(int row, int colbytes) {
    return (uint32_t)(row * 128 + (colbytes ^ ((row & 7) << 4)));
}

// ================= fp32 -> fp16 convert =================
__global__ __launch_bounds__(256) void conv_f16(const float4* __restrict__ src,
                                                __half2* __restrict__ dst, int n4) {
    int i = blockIdx.x * 256 + threadIdx.x;
    if (i >= n4) return;
    float4 v = src[i];
    dst[i * 2 + 0] = __float22half2_rn(make_float2(v.x, v.y));
    dst[i * 2 + 1] = __float22half2_rn(make_float2(v.z, v.w));
}

// ================= fp16 GEMM mainloop (128x128 tile, K=2048) =================
// 8 warps of 64x32, K-tile 64, 3-stage cp.async pipeline, 96KB smem, 2 CTAs/SM.

#define KT 64
#define NKT (DDIM / KT)         // 32
#define TILE_B 16384            // 128 rows * 128 bytes (64 halves)
#define STG_B (2 * TILE_B)      // A tile + B tile
#define NSTAGE 3
#define SMEM_SZ (NSTAGE * STG_B)  // 98304

__device__ __forceinline__ void gemm_mainloop(
    const __half* __restrict__ A, int arow0, int alim,
    const __half* __restrict__ B, int brow0, int blim,
    char* smem, uint32_t sb, int tid, float acc[4][4][4])
{
    int lane = tid & 31, wid = tid >> 5;
    int wm = (wid >> 2) * 64, wn = (wid & 3) * 32;

#pragma unroll
    for (int mf = 0; mf < 4; mf++)
#pragma unroll
        for (int nf = 0; nf < 4; nf++)
#pragma unroll
            for (int q = 0; q < 4; q++) acc[mf][nf][q] = 0.f;

    int crow[4], ccol[4]; uint32_t cdst[4];
#pragma unroll
    for (int it = 0; it < 4; it++) {
        int c = tid + it * 256;
        crow[it] = c >> 3; ccol[it] = c & 7;
        cdst[it] = swz(crow[it], ccol[it] * 16);
    }

#define PREFETCH(kt, s) do { \
    uint32_t st = sb + (uint32_t)(s) * STG_B; \
    int k0 = (kt) * KT; \
    _Pragma("unroll") \
    for (int it = 0; it < 4; it++) { \
        int ra = arow0 + crow[it], rb = brow0 + crow[it]; \
        cp16(st + cdst[it],          A + (size_t)ra * DDIM + k0 + ccol[it] * 8, ra < alim); \
        cp16(st + TILE_B + cdst[it], B + (size_t)rb * DDIM + k0 + ccol[it] * 8, rb < blim); \
    } \
    asm volatile("cp.async.commit_group;"); \
} while (0)

    PREFETCH(0, 0);
    PREFETCH(1, 1);

    int lr = lane & 15, kadd = (lane >> 4) * 8;

    for (int kt = 0; kt < NKT; kt++) {
        if (kt < NKT - 2) asm volatile("cp.async.wait_group 1;");
        else              asm volatile("cp.async.wait_group 0;");
        __syncthreads();

        if (kt + 2 < NKT) PREFETCH(kt + 2, (kt + 2) % NSTAGE);

        uint32_t st = sb + (uint32_t)(kt % NSTAGE) * STG_B;
        uint32_t sA = st, sB = st + TILE_B;

#pragma unroll
        for (int ks = 0; ks < 4; ks++) {
            int kc = (ks * 16 + kadd) * 2;
            uint32_t a[4][4];
#pragma unroll
            for (int mf = 0; mf < 4; mf++)
                LDSM4(a[mf], sA + swz(wm + mf * 16 + lr, kc));
            uint32_t b[4][2];
#pragma unroll
            for (int nb = 0; nb < 2; nb++) {
                uint32_t t[4];
                LDSM4(t, sB + swz(wn + nb * 16 + lr, kc));
                b[nb * 2][0] = t[0]; b[nb * 2 + 1][0] = t[1];
                b[nb * 2][1] = t[2]; b[nb * 2 + 1][1] = t[3];
            }
#pragma unroll
            for (int mf = 0; mf < 4; mf++)
#pragma unroll
                for (int nf = 0; nf < 4; nf++)
                    MMA_F16(acc[mf][nf], a[mf], b[nf]);
        }
    }
#undef PREFETCH
}

// ================= merged logits GEMM (W@W^T triangle + z@W^T) =================
__global__ __launch_bounds__(256, 2)
void gemm_logits(const __half* __restrict__ Wh, const __half* __restrict__ zh,
                 float* __restrict__ L) {
    extern __shared__ char smem[];
    uint32_t sb = smem_u32(smem);
    int tid = threadIdx.x, lane = tid & 31, wid = tid >> 5;
    int wm = (wid >> 2) * 64, wn = (wid & 3) * 32;
    int bid = blockIdx.x;
    float acc[4][4][4];

    int cr = lane >> 2, cc = (lane & 3) * 2;

    if (bid < NT1) {
        // triangle tile (r <= c) of W@W^T
        int r = 0, id = bid;
        while (id >= 8 - r) { id -= 8 - r; r++; }
        int c = r + id;
        gemm_mainloop(Wh, r * 128, CDIM, Wh, c * 128, CDIM, smem, sb, tid, acc);

#pragma unroll
        for (int mf = 0; mf < 4; mf++) {
#pragma unroll
            for (int nf = 0; nf < 4; nf++) {
                int col = c * 128 + wn + nf * 8 + cc;
                if (col >= CDIM) continue;
#pragma unroll
                for (int h = 0; h < 2; h++) {
                    int row = r * 128 + wm + mf * 16 + cr + h * 8;
                    if (row >= CDIM) continue;
                    float v0 = acc[mf][nf][h * 2 + 0], v1 = acc[mf][nf][h * 2 + 1];
                    *(float2*)(L + (size_t)row * CDIM + col) = make_float2(v0, v1);
                    if (r != c) {
                        L[(size_t)col * CDIM + row] = v0;
                        L[(size_t)(col + 1) * CDIM + row] = v1;
                    }
                }
            }
        }
    } else {
        // z@W^T tile
        int id2 = bid - NT1;
        int bm = (id2 >> 3) * 128, bn = (id2 & 7) * 128;
        gemm_mainloop(zh, bm, BDIM, Wh, bn, CDIM, smem, sb, tid, acc);

#pragma unroll
        for (int mf = 0; mf < 4; mf++) {
#pragma unroll
            for (int nf = 0; nf < 4; nf++) {
                int col = bn + wn + nf * 8 + cc;
                if (col >= CDIM) continue;
#pragma unroll
                for (int h = 0; h < 2; h++) {
                    int row = CDIM + bm + wm + mf * 16 + cr + h * 8;
                    *(float2*)(L + (size_t)row * CDIM + col) =
                        make_float2(acc[mf][nf][h * 2 + 0], acc[mf][nf][h * 2 + 1]);
                }
            }
        }
    }
}

// ================= final GEMM: out = z @ weights =================
__global__ __launch_bounds__(256, 2)
void gemm_out(const __half* __restrict__ zh, const __half* __restrict__ Ph,
              float* __restrict__ C) {
    extern __shared__ char smem[];
    uint32_t sb = smem_u32(smem);
    int tid = threadIdx.x, lane = tid & 31, wid = tid >> 5;
    int wm = (wid >> 2) * 64, wn = (wid & 3) * 32;
    int bm = (blockIdx.x >> 3) * 128, bn = (blockIdx.x & 7) * 128;
    float acc[4][4][4];
    gemm_mainloop(zh, bm, BDIM, Ph, bn, CDIM, smem, sb, tid, acc);

    int cr = lane >> 2, cc = (lane & 3) * 2;
#pragma unroll
    for (int mf = 0; mf < 4; mf++)
#pragma unroll
        for (int nf = 0; nf < 4; nf++) {
            int col = bn + wn + nf * 8 + cc;
            if (col >= CDIM) continue;
#pragma unroll
            for (int h = 0; h < 2; h++) {
                int row = bm + wm + mf * 16 + cr + h * 8;
                *(float2*)(C + (size_t)row * CDIM + col) =
                    make_float2(acc[mf][nf][h * 2 + 0], acc[mf][nf][h * 2 + 1]);
            }
        }
}

// ========== row stats: entropy + argmax with exact fp32 refinement ==========
__global__ __launch_bounds__(256) void row_stats(const float* __restrict__ L,
                                                 const float* __restrict__ Wf,
                                                 const float* __restrict__ zf) {
    __shared__ float lrow[CDIM];
    __shared__ float sv[256];
    __shared__ int   si[256];
    __shared__ float sw[256];
    __shared__ int   cand[64];
    __shared__ int   ncand;
    __shared__ float bestv; __shared__ int besti;

    int row = blockIdx.x;
    const float* l = L + (size_t)row * CDIM;
    int tid = threadIdx.x;

    // load row to smem, track per-thread max (low-index tiebreak)
    float best = -3.4e38f; int bidx = 0x7fffffff;
    for (int c = tid; c < CDIM; c += 256) {
        float v = l[c];
        lrow[c] = v;
        if (v > best || (v == best && c < bidx)) { best = v; bidx = c; }
    }
    sv[tid] = best; si[tid] = bidx;
    __syncthreads();
    for (int s = 128; s > 0; s >>= 1) {
        if (tid < s) {
            float v = sv[tid + s]; int ix = si[tid + s];
            if (v > sv[tid] || (v == sv[tid] && ix < si[tid])) { sv[tid] = v; si[tid] = ix; }
        }
        __syncthreads();
    }
    float m1 = sv[0]; int i1 = si[0];
    __syncthreads();

    // second-best value (any other class)
    float b2 = -3.4e38f;
    for (int c = tid; c < CDIM; c += 256)
        if (c != i1 && lrow[c] > b2) b2 = lrow[c];
    sv[tid] = b2;
    __syncthreads();
    for (int s = 128; s > 0; s >>= 1) {
        if (tid < s) sv[tid] = fmaxf(sv[tid], sv[tid + s]);
        __syncthreads();
    }
    float m2 = sv[0];
    __syncthreads();

    int am = i1;
    if (m1 - m2 < GAP_TH) {
        // ambiguous: refine candidates exactly in fp32 from original inputs
        if (tid == 0) { ncand = 0; bestv = -3.4e38f; besti = 0x7fffffff; }
        __syncthreads();
        for (int c = tid; c < CDIM; c += 256) {
            if (lrow[c] > m1 - GAP_TH) {
                int p = atomicAdd(&ncand, 1);
                if (p < 64) cand[p] = c;
            }
        }
        __syncthreads();
        int nc = min(ncand, 64);
        const float* arow = (row < CDIM) ? (Wf + (size_t)row * DDIM)
                                         : (zf + (size_t)(row - CDIM) * DDIM);
        for (int k = 0; k < nc; k++) {
            int c = cand[k];
            const float* brow = Wf + (size_t)c * DDIM;
            float p = 0.f;
            for (int d = tid; d < DDIM; d += 256) p = fmaf(arow[d], brow[d], p);
            sv[tid] = p;
            __syncthreads();
            for (int s = 128; s > 0; s >>= 1) {
                if (tid < s) sv[tid] += sv[tid + s];
                __syncthreads();
            }
            if (tid == 0) {
                float v = sv[0];
                if (v > bestv || (v == bestv && c < besti)) { bestv = v; besti = c; }
            }
            __syncthreads();
        }
        am = besti;
    }

    // entropy from (approximate) logits — ordering-only use downstream
    float s1 = 0.f, s2 = 0.f;
    for (int c = tid; c < CDIM; c += 256) {
        float d = lrow[c] - m1;
        float e = expf(d);
        s1 += e; s2 += e * d;
    }
    sv[tid] = s1; sw[tid] = s2;
    __syncthreads();
    for (int s = 128; s > 0; s >>= 1) {
        if (tid < s) { sv[tid] += sv[tid + s]; sw[tid] += sw[tid + s]; }
        __syncthreads();
    }
    if (tid == 0) {
        float S = sv[0], T = sw[0];
        g_ent[row]  = logf(S) - T / S;
        g_yhat[row] = am;
    }
}

// ---------------- support inverse norms ----------------
__global__ __launch_bounds__(256) void support_rnorm(const float* __restrict__ W,
                                                     const float* __restrict__ z) {
    int j = blockIdx.x;
    const float* row = (j < CDIM) ? (W + (size_t)j * DDIM)
                                  : (z + (size_t)(j - CDIM) * DDIM);
    __shared__ float red[256];
    int tid = threadIdx.x;
    float ss = 0.f;
    for (int d = tid; d < DDIM; d += 256) { float v = row[d]; ss += v * v; }
    red[tid] = ss;
    __syncthreads();
    for (int s = 128; s > 0; s >>= 1) {
        if (tid < s) red[tid] += red[tid + s];
        __syncthreads();
    }
    if (tid == 0) g_rnorm[j] = 1.f / fmaxf(sqrtf(red[0]), 1e-12f);
}

// ---------------- per-class selection + prototype accumulation ----------------
__global__ __launch_bounds__(256) void select_accum(const float* __restrict__ W,
                                                    const float* __restrict__ z,
                                                    const int* __restrict__ filterK) {
    __shared__ float ent_s[SEL_CAP];
    __shared__ int   idx_s[SEL_CAP];
    __shared__ unsigned char keep_s[SEL_CAP];
    __shared__ int   cnt;
    __shared__ float red[256];

    int c = blockIdx.x;
    int tid = threadIdx.x;
    if (tid == 0) cnt = 0;
    __syncthreads();

    for (int j = tid; j < NDIM; j += 256) {
        if (g_yhat[j] == c) {
            int p = atomicAdd(&cnt, 1);
            if (p < SEL_CAP) { ent_s[p] = g_ent[j]; idx_s[p] = j; }
        }
    }
    __syncthreads();
    int n = min(cnt, SEL_CAP);
    int K = *filterK;

    // rank-based selection (tie-break: lower support index, matching jax.lax.top_k)
    for (int i = tid; i < n; i += 256) {
        float ei = ent_s[i]; int ji = idx_s[i];
        int rank = 0;
        for (int m2 = 0; m2 < n; m2++) {
            float em = ent_s[m2]; int jm = idx_s[m2];
            rank += (em < ei) || (em == ei && jm < ji);
        }
        keep_s[i] = (rank < K) ? 1 : 0;
    }
    __syncthreads();

    float acc[DDIM / 256];
#pragma unroll
    for (int u = 0; u < DDIM / 256; u++) acc[u] = 0.f;

    for (int i = 0; i < n; i++) {
        if (!keep_s[i]) continue;
        int j = idx_s[i];
        const float* srow = (j < CDIM) ? (W + (size_t)j * DDIM)
                                       : (z + (size_t)(j - CDIM) * DDIM);
        float rn = g_rnorm[j];
#pragma unroll
        for (int u = 0; u < DDIM / 256; u++)
            acc[u] = fmaf(srow[tid + u * 256], rn, acc[u]);
    }

    float ss = 0.f;
#pragma unroll
    for (int u = 0; u < DDIM / 256; u++) ss += acc[u] * acc[u];
    red[tid] = ss;
    __syncthreads();
    for (int s = 128; s > 0; s >>= 1) {
        if (tid < s) red[tid] += red[tid + s];
        __syncthreads();
    }
    float inv = 1.f / fmaxf(sqrtf(red[0]), 1e-12f);
#pragma unroll
    for (int u = 0; u < DDIM / 256; u++)
        g_Ph[(size_t)c * DDIM + tid + u * 256] = __float2half_rn(acc[u] * inv);
}

// ---------------- launch ----------------
extern "C" void kernel_launch(void* const* d_in, const int* in_sizes, int n_in,
                              void* d_out, int out_size) {
    const float* z  = (const float*)d_in[0];   // [4096, 2048]
    const float* W  = (const float*)d_in[1];   // [1000, 2048]
    const int*   fK = (const int*)d_in[2];     // scalar filter_K
    float* out = (float*)d_out;                // [4096, 1000]

    float* L;
    __half *zh, *Wh, *Ph;
    cudaGetSymbolAddress((void**)&L,  g_L);
    cudaGetSymbolAddress((void**)&zh, g_zh);
    cudaGetSymbolAddress((void**)&Wh, g_Wh);
    cudaGetSymbolAddress((void**)&Ph, g_Ph);

    cudaFuncSetAttribute(gemm_logits, cudaFuncAttributeMaxDynamicSharedMemorySize, SMEM_SZ);
    cudaFuncSetAttribute(gemm_out,    cudaFuncAttributeMaxDynamicSharedMemorySize, SMEM_SZ);

    dim3 thr(256);
    // fp16 conversions
    int n4z = BDIM * DDIM / 4, n4w = CDIM * DDIM / 4;
    conv_f16<<<(n4z + 255) / 256, thr>>>((const float4*)z, (__half2*)zh, n4z);
    conv_f16<<<(n4w + 255) / 256, thr>>>((const float4*)W, (__half2*)Wh, n4w);

    // all logits in one launch: W@W^T (triangle, mirrored) + z@W^T
    gemm_logits<<<NT1 + NT2, thr, SMEM_SZ>>>(Wh, zh, L);

    // entropy + argmax (exact-refined) for all 5096 supports
    row_stats<<<NDIM, thr>>>(L, W, z);

    // support norms + selection + prototypes (fp16)
    support_rnorm<<<NDIM, thr>>>(W, z);
    select_accum<<<CDIM, thr>>>(W, z, fK);

    // final logits: z @ weights
    gemm_out<<<NT2, thr, SMEM_SZ>>>(zh, Ph, out);
}

// round 11
// speedup vs baseline: 6.9344x; 1.1094x over previous
#include <cuda_runtime.h>
#include <cuda_fp16.h>
#include <math.h>
#include <stdint.h>

// Problem dims (fixed by the dataset)
#define BDIM 4096
#define CDIM 1000
#define DDIM 2048
#define NDIM (BDIM + CDIM)   // 5096 supports
#define SEL_CAP 5120
#define NT1 36               // triangle tiles for W@W^T (8x8, r<=c)
#define NT2 256              // tiles for z@W^T (32x8)
#define GAP_TH 0.02f         // refine argmax when top-2 gap below this

// ---------------- scratch (device globals; no allocs allowed) ----------------
__device__ float  g_L[NDIM * CDIM];     // all logits: rows 0..999 = W@W^T, 1000.. = z@W^T
__device__ float  g_ent[NDIM];
__device__ int    g_yhat[NDIM];
__device__ float  g_rnorm[NDIM];
__device__ __half g_zh[BDIM * DDIM];
__device__ __half g_Wh[CDIM * DDIM];
__device__ __half g_Ph[CDIM * DDIM];    // prototype (weights^T) fp16

// ================= helpers =================
__device__ __forceinline__ uint32_t smem_u32(const void* p) {
    uint32_t a;
    asm("{ .reg .u64 t; cvta.to.shared.u64 t, %1; cvt.u32.u64 %0, t; }" : "=r"(a) : "l"(p));
    return a;
}

__device__ __forceinline__ void cp16(uint32_t dst, const void* src, bool v) {
    int n = v ? 16 : 0;
    asm volatile("cp.async.cg.shared.global [%0], [%1], 16, %2;"
                 :: "r"(dst), "l"(src), "r"(n) : "memory");
}

#define LDSM4(r, addr) \
    asm volatile("ldmatrix.sync.aligned.m8n8.x4.shared.b16 {%0,%1,%2,%3}, [%4];" \
        : "=r"((r)[0]), "=r"((r)[1]), "=r"((r)[2]), "=r"((r)[3]) : "r"(addr))

#define MMA_F16(acc, a, b) \
    asm volatile("mma.sync.aligned.m16n8k16.row.col.f32.f16.f16.f32 " \
        "{%0,%1,%2,%3}, {%4,%5,%6,%7}, {%8,%9}, {%0,%1,%2,%3};" \
        : "+f"((acc)[0]), "+f"((acc)[1]), "+f"((acc)[2]), "+f"((acc)[3]) \
        : "r"((a)[0]), "r"((a)[1]), "r"((a)[2]), "r"((a)[3]), \
          "r"((b)[0]), "r"((b)[1]))

// swizzled byte offset inside a 128-row x 128B tile (SW128 pattern)
__device__ __forceinline__ uint32_t swz(int row, int colbytes) {
    return (uint32_t)(row * 128 + (colbytes ^ ((row & 7) << 4)));
}

// ============ fused fp32->fp16 convert + row inverse-norm ============
// One block per support row: convert to fp16 dst, reduce sum-of-squares.
__global__ __launch_bounds__(256) void conv_rnorm(const float* __restrict__ W,
                                                  const float* __restrict__ z,
                                                  __half* __restrict__ Wh,
                                                  __half* __restrict__ zh) {
    int j = blockIdx.x;
    const float4* src;
    __half2* dst;
    if (j < CDIM) {
        src = (const float4*)(W + (size_t)j * DDIM);
        dst = (__half2*)(Wh + (size_t)j * DDIM);
    } else {
        src = (const float4*)(z + (size_t)(j - CDIM) * DDIM);
        dst = (__half2*)(zh + (size_t)(j - CDIM) * DDIM);
    }
    int tid = threadIdx.x;
    float ss = 0.f;
#pragma unroll
    for (int u = 0; u < 2; u++) {
        int i = tid + u * 256;          // float4 index, 512 per row
        float4 v = src[i];
        dst[i * 2 + 0] = __float22half2_rn(make_float2(v.x, v.y));
        dst[i * 2 + 1] = __float22half2_rn(make_float2(v.z, v.w));
        ss += v.x * v.x + v.y * v.y + v.z * v.z + v.w * v.w;
    }
#pragma unroll
    for (int o = 16; o > 0; o >>= 1) ss += __shfl_xor_sync(0xffffffffu, ss, o);
    __shared__ float wsum[8];
    if ((tid & 31) == 0) wsum[tid >> 5] = ss;
    __syncthreads();
    if (tid == 0) {
        float t = 0.f;
#pragma unroll
        for (int w = 0; w < 8; w++) t += wsum[w];
        g_rnorm[j] = 1.f / fmaxf(sqrtf(t), 1e-12f);
    }
}

// ================= fp16 GEMM mainloop (128x128 tile, K=2048) =================
#define KT 64
#define NKT (DDIM / KT)         // 32
#define TILE_B 16384            // 128 rows * 128 bytes (64 halves)
#define STG_B (2 * TILE_B)      // A tile + B tile
#define NSTAGE 3
#define SMEM_SZ (NSTAGE * STG_B)  // 98304

__device__ __forceinline__ void gemm_mainloop(
    const __half* __restrict__ A, int arow0, int alim,
    const __half* __restrict__ B, int brow0, int blim,
    char* smem, uint32_t sb, int tid, float acc[4][4][4])
{
    int lane = tid & 31, wid = tid >> 5;
    int wm = (wid >> 2) * 64, wn = (wid & 3) * 32;

#pragma unroll
    for (int mf = 0; mf < 4; mf++)
#pragma unroll
        for (int nf = 0; nf < 4; nf++)
#pragma unroll
            for (int q = 0; q < 4; q++) acc[mf][nf][q] = 0.f;

    int crow[4], ccol[4]; uint32_t cdst[4];
#pragma unroll
    for (int it = 0; it < 4; it++) {
        int c = tid + it * 256;
        crow[it] = c >> 3; ccol[it] = c & 7;
        cdst[it] = swz(crow[it], ccol[it] * 16);
    }

#define PREFETCH(kt, s) do { \
    uint32_t st = sb + (uint32_t)(s) * STG_B; \
    int k0 = (kt) * KT; \
    _Pragma("unroll") \
    for (int it = 0; it < 4; it++) { \
        int ra = arow0 + crow[it], rb = brow0 + crow[it]; \
        cp16(st + cdst[it],          A + (size_t)ra * DDIM + k0 + ccol[it] * 8, ra < alim); \
        cp16(st + TILE_B + cdst[it], B + (size_t)rb * DDIM + k0 + ccol[it] * 8, rb < blim); \
    } \
    asm volatile("cp.async.commit_group;"); \
} while (0)

    PREFETCH(0, 0);
    PREFETCH(1, 1);

    int lr = lane & 15, kadd = (lane >> 4) * 8;

    for (int kt = 0; kt < NKT; kt++) {
        if (kt < NKT - 2) asm volatile("cp.async.wait_group 1;");
        else              asm volatile("cp.async.wait_group 0;");
        __syncthreads();

        if (kt + 2 < NKT) PREFETCH(kt + 2, (kt + 2) % NSTAGE);

        uint32_t st = sb + (uint32_t)(kt % NSTAGE) * STG_B;
        uint32_t sA = st, sB = st + TILE_B;

#pragma unroll
        for (int ks = 0; ks < 4; ks++) {
            int kc = (ks * 16 + kadd) * 2;
            uint32_t a[4][4];
#pragma unroll
            for (int mf = 0; mf < 4; mf++)
                LDSM4(a[mf], sA + swz(wm + mf * 16 + lr, kc));
            uint32_t b[4][2];
#pragma unroll
            for (int nb = 0; nb < 2; nb++) {
                uint32_t t[4];
                LDSM4(t, sB + swz(wn + nb * 16 + lr, kc));
                b[nb * 2][0] = t[0]; b[nb * 2 + 1][0] = t[1];
                b[nb * 2][1] = t[2]; b[nb * 2 + 1][1] = t[3];
            }
#pragma unroll
            for (int mf = 0; mf < 4; mf++)
#pragma unroll
                for (int nf = 0; nf < 4; nf++)
                    MMA_F16(acc[mf][nf], a[mf], b[nf]);
        }
    }
#undef PREFETCH
}

// ================= merged logits GEMM (W@W^T triangle + z@W^T) =================
__global__ __launch_bounds__(256, 2)
void gemm_logits(const __half* __restrict__ Wh, const __half* __restrict__ zh,
                 float* __restrict__ L) {
    extern __shared__ char smem[];
    uint32_t sb = smem_u32(smem);
    int tid = threadIdx.x, lane = tid & 31, wid = tid >> 5;
    int wm = (wid >> 2) * 64, wn = (wid & 3) * 32;
    int bid = blockIdx.x;
    float acc[4][4][4];

    int cr = lane >> 2, cc = (lane & 3) * 2;

    if (bid < NT1) {
        int r = 0, id = bid;
        while (id >= 8 - r) { id -= 8 - r; r++; }
        int c = r + id;
        gemm_mainloop(Wh, r * 128, CDIM, Wh, c * 128, CDIM, smem, sb, tid, acc);

#pragma unroll
        for (int mf = 0; mf < 4; mf++) {
#pragma unroll
            for (int nf = 0; nf < 4; nf++) {
                int col = c * 128 + wn + nf * 8 + cc;
                if (col >= CDIM) continue;
#pragma unroll
                for (int h = 0; h < 2; h++) {
                    int row = r * 128 + wm + mf * 16 + cr + h * 8;
                    if (row >= CDIM) continue;
                    float v0 = acc[mf][nf][h * 2 + 0], v1 = acc[mf][nf][h * 2 + 1];
                    *(float2*)(L + (size_t)row * CDIM + col) = make_float2(v0, v1);
                    if (r != c) {
                        L[(size_t)col * CDIM + row] = v0;
                        L[(size_t)(col + 1) * CDIM + row] = v1;
                    }
                }
            }
        }
    } else {
        int id2 = bid - NT1;
        int bm = (id2 >> 3) * 128, bn = (id2 & 7) * 128;
        gemm_mainloop(zh, bm, BDIM, Wh, bn, CDIM, smem, sb, tid, acc);

#pragma unroll
        for (int mf = 0; mf < 4; mf++) {
#pragma unroll
            for (int nf = 0; nf < 4; nf++) {
                int col = bn + wn + nf * 8 + cc;
                if (col >= CDIM) continue;
#pragma unroll
                for (int h = 0; h < 2; h++) {
                    int row = CDIM + bm + wm + mf * 16 + cr + h * 8;
                    *(float2*)(L + (size_t)row * CDIM + col) =
                        make_float2(acc[mf][nf][h * 2 + 0], acc[mf][nf][h * 2 + 1]);
                }
            }
        }
    }
}

// ================= final GEMM: out = z @ weights =================
__global__ __launch_bounds__(256, 2)
void gemm_out(const __half* __restrict__ zh, const __half* __restrict__ Ph,
              float* __restrict__ C) {
    extern __shared__ char smem[];
    uint32_t sb = smem_u32(smem);
    int tid = threadIdx.x, lane = tid & 31, wid = tid >> 5;
    int wm = (wid >> 2) * 64, wn = (wid & 3) * 32;
    int bm = (blockIdx.x >> 3) * 128, bn = (blockIdx.x & 7) * 128;
    float acc[4][4][4];
    gemm_mainloop(zh, bm, BDIM, Ph, bn, CDIM, smem, sb, tid, acc);

    int cr = lane >> 2, cc = (lane & 3) * 2;
#pragma unroll
    for (int mf = 0; mf < 4; mf++)
#pragma unroll
        for (int nf = 0; nf < 4; nf++) {
            int col = bn + wn + nf * 8 + cc;
            if (col >= CDIM) continue;
#pragma unroll
            for (int h = 0; h < 2; h++) {
                int row = bm + wm + mf * 16 + cr + h * 8;
                *(float2*)(C + (size_t)row * CDIM + col) =
                    make_float2(acc[mf][nf][h * 2 + 0], acc[mf][nf][h * 2 + 1]);
            }
        }
}

// ========== row stats: online top-2 + entropy in one pass ==========
// State: (m1, i1, m2, s1, s2); s1 = sum exp(l-m1), s2 = sum (l-m1)exp(l-m1).
struct RS { float m1; int i1; float m2; float s1; float s2; };

__device__ __forceinline__ RS rs_merge(RS a, RS b) {
    if (b.m1 == -3.4e38f) return a;
    if (a.m1 == -3.4e38f) return b;
    RS r;
    bool a_wins = (a.m1 > b.m1) || (a.m1 == b.m1 && a.i1 < b.i1);
    RS hi = a_wins ? a : b;
    RS lo = a_wins ? b : a;
    r.m1 = hi.m1; r.i1 = hi.i1;
    r.m2 = fmaxf(fmaxf(hi.m2, lo.m2), lo.m1);
    float d = lo.m1 - hi.m1;           // <= 0
    float f = __expf(d);
    r.s1 = hi.s1 + f * lo.s1;
    r.s2 = hi.s2 + f * (lo.s2 + d * lo.s1);
    return r;
}

__global__ __launch_bounds__(256) void row_stats(const float* __restrict__ L,
                                                 const float* __restrict__ Wf,
                                                 const float* __restrict__ zf) {
    __shared__ float sv[256];
    __shared__ RS wstate[8];
    __shared__ int  cand[64];
    __shared__ int  ncand;
    __shared__ float bestv; __shared__ int besti;
    __shared__ RS rowst;

    int row = blockIdx.x;
    const float* l = L + (size_t)row * CDIM;
    int tid = threadIdx.x;

    RS st; st.m1 = -3.4e38f; st.i1 = 0x7fffffff; st.m2 = -3.4e38f; st.s1 = 0.f; st.s2 = 0.f;
    for (int c = tid; c < CDIM; c += 256) {
        float v = l[c];
        if (v > st.m1) {
            float d = st.m1 - v;                    // < 0 (or -inf first time)
            float f = (st.m1 == -3.4e38f) ? 0.f : __expf(d);
            st.s2 = f * (st.s2 + d * st.s1) + 0.f;  // new element contributes 0 to s2
            st.s1 = f * st.s1 + 1.f;
            st.m2 = st.m1;
            st.m1 = v; st.i1 = c;
        } else {
            float d = v - st.m1;
            float e = __expf(d);
            st.s1 += e; st.s2 += d * e;
            if (v > st.m2) st.m2 = v;
        }
    }
    // warp merge
#pragma unroll
    for (int o = 16; o > 0; o >>= 1) {
        RS ot;
        ot.m1 = __shfl_xor_sync(0xffffffffu, st.m1, o);
        ot.i1 = __shfl_xor_sync(0xffffffffu, st.i1, o);
        ot.m2 = __shfl_xor_sync(0xffffffffu, st.m2, o);
        ot.s1 = __shfl_xor_sync(0xffffffffu, st.s1, o);
        ot.s2 = __shfl_xor_sync(0xffffffffu, st.s2, o);
        st = rs_merge(st, ot);
    }
    if ((tid & 31) == 0) wstate[tid >> 5] = st;
    __syncthreads();
    if (tid == 0) {
        RS t = wstate[0];
#pragma unroll
        for (int w = 1; w < 8; w++) t = rs_merge(t, wstate[w]);
        rowst = t;
        ncand = 0; bestv = -3.4e38f; besti = 0x7fffffff;
    }
    __syncthreads();
    RS fin = rowst;
    int am = fin.i1;

    if (fin.m1 - fin.m2 < GAP_TH) {
        // ambiguous argmax: collect candidates, refine exactly in fp32
        for (int c = tid; c < CDIM; c += 256) {
            if (l[c] > fin.m1 - GAP_TH) {
                int p = atomicAdd(&ncand, 1);
                if (p < 64) cand[p] = c;
            }
        }
        __syncthreads();
        int nc = min(ncand, 64);
        const float* arow = (row < CDIM) ? (Wf + (size_t)row * DDIM)
                                         : (zf + (size_t)(row - CDIM) * DDIM);
        for (int k = 0; k < nc; k++) {
            int c = cand[k];
            const float* brow = Wf + (size_t)c * DDIM;
            float p = 0.f;
            for (int d = tid; d < DDIM; d += 256) p = fmaf(arow[d], brow[d], p);
#pragma unroll
            for (int o = 16; o > 0; o >>= 1) p += __shfl_xor_sync(0xffffffffu, p, o);
            if ((tid & 31) == 0) sv[tid >> 5] = p;
            __syncthreads();
            if (tid == 0) {
                float v = 0.f;
#pragma unroll
                for (int w = 0; w < 8; w++) v += sv[w];
                if (v > bestv || (v == bestv && c < besti)) { bestv = v; besti = c; }
            }
            __syncthreads();
        }
        am = besti;
    }

    if (tid == 0) {
        g_ent[row]  = logf(fin.s1) - fin.s2 / fin.s1;
        g_yhat[row] = am;
    }
}

// ---------------- per-class selection + prototype accumulation ----------------
__global__ __launch_bounds__(256) void select_accum(const float* __restrict__ W,
                                                    const float* __restrict__ z,
                                                    const int* __restrict__ filterK) {
    __shared__ float ent_s[SEL_CAP];
    __shared__ int   idx_s[SEL_CAP];
    __shared__ unsigned char keep_s[SEL_CAP];
    __shared__ int   cnt;
    __shared__ float red[256];

    int c = blockIdx.x;
    int tid = threadIdx.x;
    if (tid == 0) cnt = 0;
    __syncthreads();

    for (int j = tid; j < NDIM; j += 256) {
        if (g_yhat[j] == c) {
            int p = atomicAdd(&cnt, 1);
            if (p < SEL_CAP) { ent_s[p] = g_ent[j]; idx_s[p] = j; }
        }
    }
    __syncthreads();
    int n = min(cnt, SEL_CAP);
    int K = *filterK;

    // rank-based selection (tie-break: lower support index, matching jax.lax.top_k)
    for (int i = tid; i < n; i += 256) {
        float ei = ent_s[i]; int ji = idx_s[i];
        int rank = 0;
        for (int m2 = 0; m2 < n; m2++) {
            float em = ent_s[m2]; int jm = idx_s[m2];
            rank += (em < ei) || (em == ei && jm < ji);
        }
        keep_s[i] = (rank < K) ? 1 : 0;
    }
    __syncthreads();

    float acc[DDIM / 256];
#pragma unroll
    for (int u = 0; u < DDIM / 256; u++) acc[u] = 0.f;

    for (int i = 0; i < n; i++) {
        if (!keep_s[i]) continue;
        int j = idx_s[i];
        const float* srow = (j < CDIM) ? (W + (size_t)j * DDIM)
                                       : (z + (size_t)(j - CDIM) * DDIM);
        float rn = g_rnorm[j];
#pragma unroll
        for (int u = 0; u < DDIM / 256; u++)
            acc[u] = fmaf(srow[tid + u * 256], rn, acc[u]);
    }

    float ss = 0.f;
#pragma unroll
    for (int u = 0; u < DDIM / 256; u++) ss += acc[u] * acc[u];
    red[tid] = ss;
    __syncthreads();
    for (int s = 128; s > 0; s >>= 1) {
        if (tid < s) red[tid] += red[tid + s];
        __syncthreads();
    }
    float inv = 1.f / fmaxf(sqrtf(red[0]), 1e-12f);
#pragma unroll
    for (int u = 0; u < DDIM / 256; u++)
        g_Ph[(size_t)c * DDIM + tid + u * 256] = __float2half_rn(acc[u] * inv);
}

// ---------------- launch ----------------
extern "C" void kernel_launch(void* const* d_in, const int* in_sizes, int n_in,
                              void* d_out, int out_size) {
    const float* z  = (const float*)d_in[0];   // [4096, 2048]
    const float* W  = (const float*)d_in[1];   // [1000, 2048]
    const int*   fK = (const int*)d_in[2];     // scalar filter_K
    float* out = (float*)d_out;                // [4096, 1000]

    float* L;
    __half *zh, *Wh, *Ph;
    cudaGetSymbolAddress((void**)&L,  g_L);
    cudaGetSymbolAddress((void**)&zh, g_zh);
    cudaGetSymbolAddress((void**)&Wh, g_Wh);
    cudaGetSymbolAddress((void**)&Ph, g_Ph);

    cudaFuncSetAttribute(gemm_logits, cudaFuncAttributeMaxDynamicSharedMemorySize, SMEM_SZ);
    cudaFuncSetAttribute(gemm_out,    cudaFuncAttributeMaxDynamicSharedMemorySize, SMEM_SZ);

    dim3 thr(256);
    // fused fp16 conversion + inverse norms (one block per support row)
    conv_rnorm<<<NDIM, thr>>>(W, z, Wh, zh);

    // all logits in one launch: W@W^T (triangle, mirrored) + z@W^T
    gemm_logits<<<NT1 + NT2, thr, SMEM_SZ>>>(Wh, zh, L);

    // entropy + argmax (online, exact-refined) for all 5096 supports
    row_stats<<<NDIM, thr>>>(L, W, z);

    // selection + prototypes (fp16)
    select_accum<<<CDIM, thr>>>(W, z, fK);

    // final logits: z @ weights
    gemm_out<<<NT2, thr, SMEM_SZ>>>(zh, Ph, out);
}

// round 13
// speedup vs baseline: 7.0131x; 1.0113x over previous
#include <cuda_runtime.h>
#include <cuda_fp16.h>
#include <math.h>
#include <stdint.h>

// Problem dims (fixed by the dataset)
#define BDIM 4096
#define CDIM 1000
#define DDIM 2048
#define NDIM (BDIM + CDIM)   // 5096 supports
#define NT1 36               // triangle tiles for W@W^T (8x8, r<=c)
#define NT2 256              // tiles for z@W^T (32x8)
#define GAP_TH 0.02f         // refine argmax when top-2 gap below this

// ---------------- scratch (device globals; no allocs allowed) ----------------
__device__ float  g_L[NDIM * CDIM];     // all logits
__device__ float  g_ent[NDIM];
__device__ int    g_yhat[NDIM];
__device__ float  g_rnorm[NDIM];
__device__ int    g_cnt[CDIM];          // per-class member count
__device__ int    g_off[CDIM];          // exclusive scan of counts
__device__ int    g_pos[CDIM];          // scatter cursor
__device__ float  g_gent[NDIM];         // class-grouped entropies
__device__ int    g_gidx[NDIM];         // class-grouped support indices
__device__ __half g_zh[BDIM * DDIM];
__device__ __half g_Wh[CDIM * DDIM];
__device__ __half g_Ph[CDIM * DDIM];    // prototype (weights^T) fp16

// ================= helpers =================
__device__ __forceinline__ uint32_t smem_u32(const void* p) {
    uint32_t a;
    asm("{ .reg .u64 t; cvta.to.shared.u64 t, %1; cvt.u32.u64 %0, t; }" : "=r"(a) : "l"(p));
    return a;
}

__device__ __forceinline__ void cp16(uint32_t dst, const void* src, bool v) {
    int n = v ? 16 : 0;
    asm volatile("cp.async.cg.shared.global [%0], [%1], 16, %2;"
                 :: "r"(dst), "l"(src), "r"(n) : "memory");
}

#define LDSM4(r, addr) \
    asm volatile("ldmatrix.sync.aligned.m8n8.x4.shared.b16 {%0,%1,%2,%3}, [%4];" \
        : "=r"((r)[0]), "=r"((r)[1]), "=r"((r)[2]), "=r"((r)[3]) : "r"(addr))

#define MMA_F16(acc, a, b) \
    asm volatile("mma.sync.aligned.m16n8k16.row.col.f32.f16.f16.f32 " \
        "{%0,%1,%2,%3}, {%4,%5,%6,%7}, {%8,%9}, {%0,%1,%2,%3};" \
        : "+f"((acc)[0]), "+f"((acc)[1]), "+f"((acc)[2]), "+f"((acc)[3]) \
        : "r"((a)[0]), "r"((a)[1]), "r"((a)[2]), "r"((a)[3]), \
          "r"((b)[0]), "r"((b)[1]))

__device__ __forceinline__ uint32_t swz(int row, int colbytes) {
    return (uint32_t)(row * 128 + (colbytes ^ ((row & 7) << 4)));
}

// ============ fused fp32->fp16 convert + row inverse-norm ============
__global__ __launch_bounds__(256) void conv_rnorm(const float* __restrict__ W,
                                                  const float* __restrict__ z,
                                                  __half* __restrict__ Wh,
                                                  __half* __restrict__ zh) {
    int j = blockIdx.x;
    const float4* src;
    __half2* dst;
    if (j < CDIM) {
        src = (const float4*)(W + (size_t)j * DDIM);
        dst = (__half2*)(Wh + (size_t)j * DDIM);
    } else {
        src = (const float4*)(z + (size_t)(j - CDIM) * DDIM);
        dst = (__half2*)(zh + (size_t)(j - CDIM) * DDIM);
    }
    int tid = threadIdx.x;
    float ss = 0.f;
#pragma unroll
    for (int u = 0; u < 2; u++) {
        int i = tid + u * 256;
        float4 v = src[i];
        dst[i * 2 + 0] = __float22half2_rn(make_float2(v.x, v.y));
        dst[i * 2 + 1] = __float22half2_rn(make_float2(v.z, v.w));
        ss += v.x * v.x + v.y * v.y + v.z * v.z + v.w * v.w;
    }
#pragma unroll
    for (int o = 16; o > 0; o >>= 1) ss += __shfl_xor_sync(0xffffffffu, ss, o);
    __shared__ float wsum[8];
    if ((tid & 31) == 0) wsum[tid >> 5] = ss;
    __syncthreads();
    if (tid == 0) {
        float t = 0.f;
#pragma unroll
        for (int w = 0; w < 8; w++) t += wsum[w];
        g_rnorm[j] = 1.f / fmaxf(sqrtf(t), 1e-12f);
    }
}

// ================= fp16 GEMM mainloop (128x128 tile, K=2048) =================
#define KT 64
#define NKT (DDIM / KT)         // 32
#define TILE_B 16384
#define STG_B (2 * TILE_B)
#define NSTAGE 3
#define SMEM_SZ (NSTAGE * STG_B)  // 98304

__device__ __forceinline__ void gemm_mainloop(
    const __half* __restrict__ A, int arow0, int alim,
    const __half* __restrict__ B, int brow0, int blim,
    char* smem, uint32_t sb, int tid, float acc[4][4][4])
{
    int lane = tid & 31, wid = tid >> 5;
    int wm = (wid >> 2) * 64, wn = (wid & 3) * 32;

#pragma unroll
    for (int mf = 0; mf < 4; mf++)
#pragma unroll
        for (int nf = 0; nf < 4; nf++)
#pragma unroll
            for (int q = 0; q < 4; q++) acc[mf][nf][q] = 0.f;

    int crow[4], ccol[4]; uint32_t cdst[4];
#pragma unroll
    for (int it = 0; it < 4; it++) {
        int c = tid + it * 256;
        crow[it] = c >> 3; ccol[it] = c & 7;
        cdst[it] = swz(crow[it], ccol[it] * 16);
    }

#define PREFETCH(kt, s) do { \
    uint32_t st = sb + (uint32_t)(s) * STG_B; \
    int k0 = (kt) * KT; \
    _Pragma("unroll") \
    for (int it = 0; it < 4; it++) { \
        int ra = arow0 + crow[it], rb = brow0 + crow[it]; \
        cp16(st + cdst[it],          A + (size_t)ra * DDIM + k0 + ccol[it] * 8, ra < alim); \
        cp16(st + TILE_B + cdst[it], B + (size_t)rb * DDIM + k0 + ccol[it] * 8, rb < blim); \
    } \
    asm volatile("cp.async.commit_group;"); \
} while (0)

    PREFETCH(0, 0);
    PREFETCH(1, 1);

    int lr = lane & 15, kadd = (lane >> 4) * 8;

    for (int kt = 0; kt < NKT; kt++) {
        if (kt < NKT - 2) asm volatile("cp.async.wait_group 1;");
        else              asm volatile("cp.async.wait_group 0;");
        __syncthreads();

        if (kt + 2 < NKT) PREFETCH(kt + 2, (kt + 2) % NSTAGE);

        uint32_t st = sb + (uint32_t)(kt % NSTAGE) * STG_B;
        uint32_t sA = st, sB = st + TILE_B;

#pragma unroll
        for (int ks = 0; ks < 4; ks++) {
            int kc = (ks * 16 + kadd) * 2;
            uint32_t a[4][4];
#pragma unroll
            for (int mf = 0; mf < 4; mf++)
                LDSM4(a[mf], sA + swz(wm + mf * 16 + lr, kc));
            uint32_t b[4][2];
#pragma unroll
            for (int nb = 0; nb < 2; nb++) {
                uint32_t t[4];
                LDSM4(t, sB + swz(wn + nb * 16 + lr, kc));
                b[nb * 2][0] = t[0]; b[nb * 2 + 1][0] = t[1];
                b[nb * 2][1] = t[2]; b[nb * 2 + 1][1] = t[3];
            }
#pragma unroll
            for (int mf = 0; mf < 4; mf++)
#pragma unroll
                for (int nf = 0; nf < 4; nf++)
                    MMA_F16(acc[mf][nf], a[mf], b[nf]);
        }
    }
#undef PREFETCH
}

// ================= merged logits GEMM (W@W^T triangle + z@W^T) =================
__global__ __launch_bounds__(256, 2)
void gemm_logits(const __half* __restrict__ Wh, const __half* __restrict__ zh,
                 float* __restrict__ L) {
    extern __shared__ char smem[];
    uint32_t sb = smem_u32(smem);
    int tid = threadIdx.x, lane = tid & 31, wid = tid >> 5;
    int wm = (wid >> 2) * 64, wn = (wid & 3) * 32;
    int bid = blockIdx.x;
    float acc[4][4][4];

    int cr = lane >> 2, cc = (lane & 3) * 2;

    if (bid < NT1) {
        int r = 0, id = bid;
        while (id >= 8 - r) { id -= 8 - r; r++; }
        int c = r + id;
        gemm_mainloop(Wh, r * 128, CDIM, Wh, c * 128, CDIM, smem, sb, tid, acc);

#pragma unroll
        for (int mf = 0; mf < 4; mf++) {
#pragma unroll
            for (int nf = 0; nf < 4; nf++) {
                int col = c * 128 + wn + nf * 8 + cc;
                if (col >= CDIM) continue;
#pragma unroll
                for (int h = 0; h < 2; h++) {
                    int row = r * 128 + wm + mf * 16 + cr + h * 8;
                    if (row >= CDIM) continue;
                    float v0 = acc[mf][nf][h * 2 + 0], v1 = acc[mf][nf][h * 2 + 1];
                    *(float2*)(L + (size_t)row * CDIM + col) = make_float2(v0, v1);
                    if (r != c) {
                        L[(size_t)col * CDIM + row] = v0;
                        L[(size_t)(col + 1) * CDIM + row] = v1;
                    }
                }
            }
        }
    } else {
        int id2 = bid - NT1;
        int bm = (id2 >> 3) * 128, bn = (id2 & 7) * 128;
        gemm_mainloop(zh, bm, BDIM, Wh, bn, CDIM, smem, sb, tid, acc);

#pragma unroll
        for (int mf = 0; mf < 4; mf++) {
#pragma unroll
            for (int nf = 0; nf < 4; nf++) {
                int col = bn + wn + nf * 8 + cc;
                if (col >= CDIM) continue;
#pragma unroll
                for (int h = 0; h < 2; h++) {
                    int row = CDIM + bm + wm + mf * 16 + cr + h * 8;
                    *(float2*)(L + (size_t)row * CDIM + col) =
                        make_float2(acc[mf][nf][h * 2 + 0], acc[mf][nf][h * 2 + 1]);
                }
            }
        }
    }
}

// ================= final GEMM: out = z @ weights =================
__global__ __launch_bounds__(256, 2)
void gemm_out(const __half* __restrict__ zh, const __half* __restrict__ Ph,
              float* __restrict__ C) {
    extern __shared__ char smem[];
    uint32_t sb = smem_u32(smem);
    int tid = threadIdx.x, lane = tid & 31, wid = tid >> 5;
    int wm = (wid >> 2) * 64, wn = (wid & 3) * 32;
    int bm = (blockIdx.x >> 3) * 128, bn = (blockIdx.x & 7) * 128;
    float acc[4][4][4];
    gemm_mainloop(zh, bm, BDIM, Ph, bn, CDIM, smem, sb, tid, acc);

    int cr = lane >> 2, cc = (lane & 3) * 2;
#pragma unroll
    for (int mf = 0; mf < 4; mf++)
#pragma unroll
        for (int nf = 0; nf < 4; nf++) {
            int col = bn + wn + nf * 8 + cc;
            if (col >= CDIM) continue;
#pragma unroll
            for (int h = 0; h < 2; h++) {
                int row = bm + wm + mf * 16 + cr + h * 8;
                *(float2*)(C + (size_t)row * CDIM + col) =
                    make_float2(acc[mf][nf][h * 2 + 0], acc[mf][nf][h * 2 + 1]);
            }
        }
}

// ================= zero counters =================
__global__ void zero_cnt() {
    int i = blockIdx.x * 256 + threadIdx.x;
    if (i < CDIM) { g_cnt[i] = 0; g_pos[i] = 0; }
}

// ========== row stats: online top-2 + entropy in one pass (+ class histogram) ==========
struct RS { float m1; int i1; float m2; float s1; float s2; };

__device__ __forceinline__ RS rs_merge(RS a, RS b) {
    if (b.m1 == -3.4e38f) return a;
    if (a.m1 == -3.4e38f) return b;
    RS r;
    bool a_wins = (a.m1 > b.m1) || (a.m1 == b.m1 && a.i1 < b.i1);
    RS hi = a_wins ? a : b;
    RS lo = a_wins ? b : a;
    r.m1 = hi.m1; r.i1 = hi.i1;
    r.m2 = fmaxf(fmaxf(hi.m2, lo.m2), lo.m1);
    float d = lo.m1 - hi.m1;
    float f = __expf(d);
    r.s1 = hi.s1 + f * lo.s1;
    r.s2 = hi.s2 + f * (lo.s2 + d * lo.s1);
    return r;
}

__global__ __launch_bounds__(256) void row_stats(const float* __restrict__ L,
                                                 const float* __restrict__ Wf,
                                                 const float* __restrict__ zf) {
    __shared__ float sv[256];
    __shared__ RS wstate[8];
    __shared__ int  cand[64];
    __shared__ int  ncand;
    __shared__ float bestv; __shared__ int besti;
    __shared__ RS rowst;

    int row = blockIdx.x;
    const float* l = L + (size_t)row * CDIM;
    int tid = threadIdx.x;

    RS st; st.m1 = -3.4e38f; st.i1 = 0x7fffffff; st.m2 = -3.4e38f; st.s1 = 0.f; st.s2 = 0.f;
    for (int c = tid; c < CDIM; c += 256) {
        float v = l[c];
        if (v > st.m1) {
            float d = st.m1 - v;
            float f = (st.m1 == -3.4e38f) ? 0.f : __expf(d);
            st.s2 = f * (st.s2 + d * st.s1);
            st.s1 = f * st.s1 + 1.f;
            st.m2 = st.m1;
            st.m1 = v; st.i1 = c;
        } else {
            float d = v - st.m1;
            float e = __expf(d);
            st.s1 += e; st.s2 += d * e;
            if (v > st.m2) st.m2 = v;
        }
    }
#pragma unroll
    for (int o = 16; o > 0; o >>= 1) {
        RS ot;
        ot.m1 = __shfl_xor_sync(0xffffffffu, st.m1, o);
        ot.i1 = __shfl_xor_sync(0xffffffffu, st.i1, o);
        ot.m2 = __shfl_xor_sync(0xffffffffu, st.m2, o);
        ot.s1 = __shfl_xor_sync(0xffffffffu, st.s1, o);
        ot.s2 = __shfl_xor_sync(0xffffffffu, st.s2, o);
        st = rs_merge(st, ot);
    }
    if ((tid & 31) == 0) wstate[tid >> 5] = st;
    __syncthreads();
    if (tid == 0) {
        RS t = wstate[0];
#pragma unroll
        for (int w = 1; w < 8; w++) t = rs_merge(t, wstate[w]);
        rowst = t;
        ncand = 0; bestv = -3.4e38f; besti = 0x7fffffff;
    }
    __syncthreads();
    RS fin = rowst;
    int am = fin.i1;

    if (fin.m1 - fin.m2 < GAP_TH) {
        for (int c = tid; c < CDIM; c += 256) {
            if (l[c] > fin.m1 - GAP_TH) {
                int p = atomicAdd(&ncand, 1);
                if (p < 64) cand[p] = c;
            }
        }
        __syncthreads();
        int nc = min(ncand, 64);
        const float* arow = (row < CDIM) ? (Wf + (size_t)row * DDIM)
                                         : (zf + (size_t)(row - CDIM) * DDIM);
        for (int k = 0; k < nc; k++) {
            int c = cand[k];
            const float* brow = Wf + (size_t)c * DDIM;
            float p = 0.f;
            for (int d = tid; d < DDIM; d += 256) p = fmaf(arow[d], brow[d], p);
#pragma unroll
            for (int o = 16; o > 0; o >>= 1) p += __shfl_xor_sync(0xffffffffu, p, o);
            if ((tid & 31) == 0) sv[tid >> 5] = p;
            __syncthreads();
            if (tid == 0) {
                float v = 0.f;
#pragma unroll
                for (int w = 0; w < 8; w++) v += sv[w];
                if (v > bestv || (v == bestv && c < besti)) { bestv = v; besti = c; }
            }
            __syncthreads();
        }
        am = besti;
    }

    if (tid == 0) {
        g_ent[row]  = logf(fin.s1) - fin.s2 / fin.s1;
        g_yhat[row] = am;
        atomicAdd(&g_cnt[am], 1);   // class histogram, fused
    }
}

// ================= exclusive scan of class counts (single block) =================
__global__ __launch_bounds__(1024) void scan_cnt() {
    __shared__ int s[1024];
    int tid = threadIdx.x;
    s[tid] = (tid < CDIM) ? g_cnt[tid] : 0;
    __syncthreads();
    // Hillis-Steele inclusive scan
    for (int o = 1; o < 1024; o <<= 1) {
        int v = (tid >= o) ? s[tid - o] : 0;
        __syncthreads();
        s[tid] += v;
        __syncthreads();
    }
    if (tid < CDIM) g_off[tid] = s[tid] - g_cnt[tid];
}

// ================= scatter supports into class-grouped order =================
__global__ __launch_bounds__(256) void scatter_grp() {
    int j = blockIdx.x * 256 + threadIdx.x;
    if (j >= NDIM) return;
    int c = g_yhat[j];
    int p = atomicAdd(&g_pos[c], 1);
    int slot = g_off[c] + p;
    g_gent[slot] = g_ent[j];
    g_gidx[slot] = j;
}

// ========== per-class prototype: members are contiguous; rank only if m > K ==========
__global__ __launch_bounds__(256) void select_accum(const float* __restrict__ W,
                                                    const float* __restrict__ z,
                                                    const int* __restrict__ filterK) {
    __shared__ uint32_t keepmask[(NDIM + 31) / 32];
    __shared__ float red[8];

    int c = blockIdx.x;
    int tid = threadIdx.x;
    int m = g_cnt[c], off = g_off[c];
    int K = *filterK;

    bool use_mask = (m > K);
    if (use_mask) {
        // rank-based selection (tie-break: lower support index, matching jax.lax.top_k)
        for (int w = tid; w < (m + 31) / 32; w += 256) keepmask[w] = 0u;
        __syncthreads();
        for (int i = tid; i < m; i += 256) {
            float ei = g_gent[off + i]; int ji = g_gidx[off + i];
            int rank = 0;
            for (int q = 0; q < m; q++) {
                float eq = g_gent[off + q]; int jq = g_gidx[off + q];
                rank += (eq < ei) || (eq == ei && jq < ji);
            }
            if (rank < K) atomicOr(&keepmask[i >> 5], 1u << (i & 31));
        }
        __syncthreads();
    }

    float acc[DDIM / 256];
#pragma unroll
    for (int u = 0; u < DDIM / 256; u++) acc[u] = 0.f;

    for (int i = 0; i < m; i++) {
        if (use_mask && !(keepmask[i >> 5] & (1u << (i & 31)))) continue;
        int j = g_gidx[off + i];
        const float* srow = (j < CDIM) ? (W + (size_t)j * DDIM)
                                       : (z + (size_t)(j - CDIM) * DDIM);
        float rn = g_rnorm[j];
#pragma unroll
        for (int u = 0; u < DDIM / 256; u++)
            acc[u] = fmaf(srow[tid + u * 256], rn, acc[u]);
    }

    // column L2 norm via warp shuffles
    float ss = 0.f;
#pragma unroll
    for (int u = 0; u < DDIM / 256; u++) ss += acc[u] * acc[u];
#pragma unroll
    for (int o = 16; o > 0; o >>= 1) ss += __shfl_xor_sync(0xffffffffu, ss, o);
    if ((tid & 31) == 0) red[tid >> 5] = ss;
    __syncthreads();
    float tot = 0.f;
#pragma unroll
    for (int w = 0; w < 8; w++) tot += red[w];
    float inv = 1.f / fmaxf(sqrtf(tot), 1e-12f);
#pragma unroll
    for (int u = 0; u < DDIM / 256; u++)
        g_Ph[(size_t)c * DDIM + tid + u * 256] = __float2half_rn(acc[u] * inv);
}

// ---------------- launch ----------------
extern "C" void kernel_launch(void* const* d_in, const int* in_sizes, int n_in,
                              void* d_out, int out_size) {
    const float* z  = (const float*)d_in[0];   // [4096, 2048]
    const float* W  = (const float*)d_in[1];   // [1000, 2048]
    const int*   fK = (const int*)d_in[2];     // scalar filter_K
    float* out = (float*)d_out;                // [4096, 1000]

    float* L;
    __half *zh, *Wh, *Ph;
    cudaGetSymbolAddress((void**)&L,  g_L);
    cudaGetSymbolAddress((void**)&zh, g_zh);
    cudaGetSymbolAddress((void**)&Wh, g_Wh);
    cudaGetSymbolAddress((void**)&Ph, g_Ph);

    cudaFuncSetAttribute(gemm_logits, cudaFuncAttributeMaxDynamicSharedMemorySize, SMEM_SZ);
    cudaFuncSetAttribute(gemm_out,    cudaFuncAttributeMaxDynamicSharedMemorySize, SMEM_SZ);

    dim3 thr(256);
    // zero class counters (overlaps nothing, trivial)
    zero_cnt<<<(CDIM + 255) / 256, thr>>>();
    // fused fp16 conversion + inverse norms
    conv_rnorm<<<NDIM, thr>>>(W, z, Wh, zh);
    // all logits in one launch
    gemm_logits<<<NT1 + NT2, thr, SMEM_SZ>>>(Wh, zh, L);
    // entropy + argmax + class histogram
    row_stats<<<NDIM, thr>>>(L, W, z);
    // group supports by class
    scan_cnt<<<1, 1024>>>();
    scatter_grp<<<(NDIM + 255) / 256, thr>>>();
    // per-class prototypes
    select_accum<<<CDIM, thr>>>(W, z, fK);
    // final logits: z @ weights
    gemm_out<<<NT2, thr, SMEM_SZ>>>(zh, Ph, out);
}